// round 11
// baseline (speedup 1.0000x reference)
#include <cuda_runtime.h>
#include <math.h>

#define N_NODES 100000
#define N_EDGES 3200000
#define D       128
#define DOUT    40

// ---------------- scratch (device globals; referenced ONLY from device code) --
// g_z:   z = x@W1_l  -> later reused for h = relu(...)
// g_agg: agg (layer1, N*D floats); later aliased as u | v | ag2 (3 * N*DOUT)
__device__ float g_z  [(size_t)N_NODES * D];
__device__ float g_agg[(size_t)N_NODES * D];
__device__ float g_inv[N_NODES];
__device__ int   g_deg[N_NODES];
__device__ int   g_rowptr[N_NODES + 1];
__device__ int   g_cur[N_NODES];
__device__ int   g_eidx[N_EDGES];

// compile-time buffer selector (device side only -> no cudaGetSymbolAddress)
// 0: g_z (z / h)   1: g_agg (agg / u)   2: v region   3: ag2 region
__device__ __forceinline__ float* sel(int id) {
    if (id == 0) return g_z;
    if (id == 1) return g_agg;
    if (id == 2) return g_agg + (size_t)N_NODES * DOUT;
    return g_agg + 2 * (size_t)N_NODES * DOUT;
}

// ---------------- CSR build ---------------------------------------------------
__global__ void k_zero_deg() {
    int i = blockIdx.x * blockDim.x + threadIdx.x;
    if (i < N_NODES) g_deg[i] = 0;
}

// edge_index is INT32 (JAX x64 disabled: "int64" request silently becomes int32)
__global__ void k_deg(const int* __restrict__ ei) {
    int e = blockIdx.x * blockDim.x + threadIdx.x;
    if (e < N_EDGES) atomicAdd(&g_deg[ei[N_EDGES + e]], 1);
}

__device__ __forceinline__ int warp_iscan(int v, int lane) {
#pragma unroll
    for (int off = 1; off < 32; off <<= 1) {
        int t = __shfl_up_sync(~0u, v, off);
        if (lane >= off) v += t;
    }
    return v;
}

// single block, 1024 threads: exclusive scan of g_deg -> g_rowptr/g_cur, plus inv
__global__ __launch_bounds__(1024) void k_scan() {
    __shared__ int wsum[32];
    __shared__ int s_carry;
    const int tid  = threadIdx.x;
    const int lane = tid & 31;
    const int wid  = tid >> 5;
    if (tid == 0) s_carry = 0;
    __syncthreads();
    for (int base = 0; base < N_NODES; base += 1024) {
        int i = base + tid;
        int v = (i < N_NODES) ? g_deg[i] : 0;
        int incl = warp_iscan(v, lane);
        if (lane == 31) wsum[wid] = incl;
        __syncthreads();
        if (wid == 0) {
            int s = wsum[lane];
            s = warp_iscan(s, lane);
            wsum[lane] = s;
        }
        __syncthreads();
        int wexcl = (wid > 0) ? wsum[wid - 1] : 0;
        int excl  = s_carry + wexcl + (incl - v);
        if (i < N_NODES) {
            g_rowptr[i] = excl;
            g_cur[i]    = excl;
            g_inv[i]    = 1.0f / fmaxf((float)v, 1.0f);
        }
        __syncthreads();                       // all reads of s_carry/wsum done
        if (tid == 0) s_carry += wsum[31];
        __syncthreads();
    }
    if (tid == 0) g_rowptr[N_NODES] = s_carry;
}

__global__ void k_fill(const int* __restrict__ ei) {
    int e = blockIdx.x * blockDim.x + threadIdx.x;
    if (e >= N_EDGES) return;
    int s = ei[e];
    int d = ei[N_EDGES + e];
    int pos = atomicAdd(&g_cur[d], 1);
    g_eidx[pos] = s;
}

// ---------------- SGEMM, K fixed = 128 ---------------------------------------
// C[M,Ncols] = A[M,128] @ B[128,Ncols] (+bias) (+epilogue)
// BM=128, BK=16, TM=TN=8. A_SEL=-1 -> A from param; else sel(A_SEL).
// EPI: 0 -> C = acc (+bias)
//      1 -> C = relu(acc + bias + agg[row,col]*inv[row])   (Ncols must be D)
template <int BN, int THREADS, int A_SEL, int C_SEL, int EPI>
__global__ __launch_bounds__(THREADS) void sgemm_k128(
    const float* __restrict__ Aparam, const float* __restrict__ B,
    const float* __restrict__ bias, int M, int Ncols)
{
    constexpr int BM = 128, BK = 16, TM = 8, TN = 8;
    __shared__ float As[BK][BM + 4];
    __shared__ float Bs[BK][BN];

    const float* A = (A_SEL < 0) ? Aparam : sel(A_SEL);
    float*       C = sel(C_SEL);

    const int tid     = threadIdx.x;
    const int rowBase = blockIdx.x * BM;
    const int tcol    = tid % (BN / TN);
    const int trow    = tid / (BN / TN);

    float acc[TM][TN];
#pragma unroll
    for (int i = 0; i < TM; i++)
#pragma unroll
        for (int j = 0; j < TN; j++) acc[i][j] = 0.f;

    for (int kt = 0; kt < D / BK; kt++) {
        for (int i = tid; i < BM * BK / 4; i += THREADS) {
            int am = i / (BK / 4);
            int ak = (i % (BK / 4)) * 4;
            float4 v = make_float4(0.f, 0.f, 0.f, 0.f);
            int row = rowBase + am;
            if (row < M)
                v = *(const float4*)(A + (size_t)row * D + kt * BK + ak);
            As[ak + 0][am] = v.x; As[ak + 1][am] = v.y;
            As[ak + 2][am] = v.z; As[ak + 3][am] = v.w;
        }
        for (int i = tid; i < BK * BN; i += THREADS) {
            int bk = i / BN, bj = i % BN;
            Bs[bk][bj] = (bj < Ncols) ? B[(size_t)(kt * BK + bk) * Ncols + bj] : 0.f;
        }
        __syncthreads();
#pragma unroll
        for (int k = 0; k < BK; k++) {
            float ra[TM], rb[TN];
#pragma unroll
            for (int i = 0; i < TM; i++) ra[i] = As[k][trow * TM + i];
#pragma unroll
            for (int j = 0; j < TN; j++) rb[j] = Bs[k][tcol * TN + j];
#pragma unroll
            for (int i = 0; i < TM; i++)
#pragma unroll
                for (int j = 0; j < TN; j++) acc[i][j] += ra[i] * rb[j];
        }
        __syncthreads();
    }

#pragma unroll
    for (int i = 0; i < TM; i++) {
        int row = rowBase + trow * TM + i;
        if (row >= M) continue;
        float inv = (EPI == 1) ? g_inv[row] : 0.f;
#pragma unroll
        for (int j = 0; j < TN; j++) {
            int col = tcol * TN + j;
            if (col >= Ncols) continue;
            float r = acc[i][j] + (bias ? bias[col] : 0.f);
            if (EPI == 1)
                r = fmaxf(fmaf(g_agg[(size_t)row * D + col], inv, r), 0.f);
            C[(size_t)row * Ncols + col] = r;
        }
    }
}

// ---------------- gather layer 1: warp per node, 128 floats = 32 x float4 -----
__device__ __forceinline__ void add4(float4& a, const float4 b) {
    a.x += b.x; a.y += b.y; a.z += b.z; a.w += b.w;
}

__global__ void k_gather128() {
    int node = (blockIdx.x * blockDim.x + threadIdx.x) >> 5;
    int lane = threadIdx.x & 31;
    if (node >= N_NODES) return;
    int beg = g_rowptr[node];
    int end = g_rowptr[node + 1];
    const float4* zz = (const float4*)g_z;
    float4 acc = make_float4(0.f, 0.f, 0.f, 0.f);
    int j = beg;
    for (; j + 3 < end; j += 4) {
        int s0 = g_eidx[j], s1 = g_eidx[j + 1];
        int s2 = g_eidx[j + 2], s3 = g_eidx[j + 3];
        float4 a = zz[(size_t)s0 * 32 + lane];
        float4 b = zz[(size_t)s1 * 32 + lane];
        float4 c = zz[(size_t)s2 * 32 + lane];
        float4 d = zz[(size_t)s3 * 32 + lane];
        add4(acc, a); add4(acc, b); add4(acc, c); add4(acc, d);
    }
    for (; j < end; j++)
        add4(acc, zz[(size_t)g_eidx[j] * 32 + lane]);
    ((float4*)g_agg)[(size_t)node * 32 + lane] = acc;
}

// ---------------- gather layer 2: warp per node, 40 floats = 10 x float4 ------
__global__ void k_gather40() {
    int node = (blockIdx.x * blockDim.x + threadIdx.x) >> 5;
    int lane = threadIdx.x & 31;
    if (node >= N_NODES || lane >= DOUT / 4) return;
    int beg = g_rowptr[node];
    int end = g_rowptr[node + 1];
    const float* u = sel(1);
    float4 acc = make_float4(0.f, 0.f, 0.f, 0.f);
    int j = beg;
    for (; j + 3 < end; j += 4) {
        int s0 = g_eidx[j], s1 = g_eidx[j + 1];
        int s2 = g_eidx[j + 2], s3 = g_eidx[j + 3];
        float4 a = ((const float4*)(u + (size_t)s0 * DOUT))[lane];
        float4 b = ((const float4*)(u + (size_t)s1 * DOUT))[lane];
        float4 c = ((const float4*)(u + (size_t)s2 * DOUT))[lane];
        float4 d = ((const float4*)(u + (size_t)s3 * DOUT))[lane];
        add4(acc, a); add4(acc, b); add4(acc, c); add4(acc, d);
    }
    for (; j < end; j++)
        add4(acc, ((const float4*)(u + (size_t)g_eidx[j] * DOUT))[lane]);
    ((float4*)(sel(3) + (size_t)node * DOUT))[lane] = acc;
}

// ---------------- final: combine + log_softmax, one warp per row --------------
__global__ void k_out(float* __restrict__ out) {
    int warp = (blockIdx.x * blockDim.x + threadIdx.x) >> 5;
    int lane = threadIdx.x & 31;
    if (warp >= N_NODES) return;
    float inv = g_inv[warp];
    const float* a = sel(3) + (size_t)warp * DOUT;  // ag2
    const float* v = sel(2) + (size_t)warp * DOUT;  // v = h@W2_r + b2
    float x0 = fmaf(a[lane], inv, v[lane]);
    float x1 = (lane < DOUT - 32) ? fmaf(a[32 + lane], inv, v[32 + lane])
                                  : -INFINITY;
    float m = fmaxf(x0, x1);
#pragma unroll
    for (int o = 16; o; o >>= 1) m = fmaxf(m, __shfl_xor_sync(~0u, m, o));
    float s = expf(x0 - m) + ((lane < DOUT - 32) ? expf(x1 - m) : 0.f);
#pragma unroll
    for (int o = 16; o; o >>= 1) s += __shfl_xor_sync(~0u, s, o);
    float lse = m + logf(s);
    out[(size_t)warp * DOUT + lane] = x0 - lse;
    if (lane < DOUT - 32) out[(size_t)warp * DOUT + 32 + lane] = x1 - lse;
}

// ---------------- launch: kernel launches ONLY (graph-capture safe) -----------
extern "C" void kernel_launch(void* const* d_in, const int* in_sizes, int n_in,
                              void* d_out, int out_size) {
    const float* x   = (const float*)d_in[0];
    const int*   ei  = (const int*)d_in[1];   // int32! (JAX default: no x64)
    const float* W1l = (const float*)d_in[2];
    const float* W1r = (const float*)d_in[3];
    const float* b1  = (const float*)d_in[4];
    const float* W2l = (const float*)d_in[5];
    const float* W2r = (const float*)d_in[6];
    const float* b2  = (const float*)d_in[7];
    float* out = (float*)d_out;

    const int gb = (N_NODES + 127) / 128;              // 782 row-blocks
    const int ge = (N_EDGES + 255) / 256;              // edge-parallel grid
    const int gw = (N_NODES * 32 + 255) / 256;         // warp-per-node grid

    // CSR build (int atomics only)
    k_zero_deg<<<(N_NODES + 255) / 256, 256>>>();
    k_deg <<<ge, 256>>>(ei);
    k_scan<<<1, 1024>>>();
    k_fill<<<ge, 256>>>(ei);

    // layer 1
    // z = x @ W1_l -> g_z
    sgemm_k128<128, 256, -1, 0, 0><<<gb, 256>>>(x, W1l, nullptr, N_NODES, D);
    // agg[d] = sum_{s in N(d)} z[s]   (deterministic CSR gather)
    k_gather128<<<gw, 256>>>();
    // h = relu(x @ W1_r + b1 + agg*inv) -> g_z (fused epilogue)
    sgemm_k128<128, 256, -1, 0, 1><<<gb, 256>>>(x, W1r, b1, N_NODES, D);

    // layer 2 (aggregate AFTER the 128->40 projection: 3.2x less gather traffic)
    // u = h @ W2_l -> sel(1)
    sgemm_k128<64, 128, 0, 1, 0><<<gb, 128>>>(nullptr, W2l, nullptr, N_NODES, DOUT);
    // v = h @ W2_r + b2 -> sel(2)
    sgemm_k128<64, 128, 0, 2, 0><<<gb, 128>>>(nullptr, W2r, b2, N_NODES, DOUT);
    // ag2[d] = sum u[s]
    k_gather40<<<gw, 256>>>();

    // out = log_softmax(ag2*inv + v)
    k_out<<<gw, 256>>>(out);
}

// round 12
// speedup vs baseline: 1.0038x; 1.0038x over previous
#include <cuda_runtime.h>
#include <math.h>

#define N_NODES 100000
#define N_EDGES 3200000
#define D       128
#define DOUT    40

// ---------------- scratch (device globals; referenced ONLY from device code) --
// g_z:   z = x@W1_l  -> later reused for h = relu(...)
// g_agg: agg (layer1, N*D floats); later aliased as u | v | ag2 (3 * N*DOUT)
__device__ float g_z  [(size_t)N_NODES * D];
__device__ float g_agg[(size_t)N_NODES * D];
__device__ float g_inv[N_NODES];
__device__ int   g_deg[N_NODES];
__device__ int   g_rowptr[N_NODES + 1];
__device__ int   g_cur[N_NODES];
__device__ int   g_eidx[N_EDGES];

// compile-time buffer selector (device side only -> no cudaGetSymbolAddress)
// 0: g_z (z / h)   1: g_agg (agg / u)   2: v region   3: ag2 region
__device__ __forceinline__ float* sel(int id) {
    if (id == 0) return g_z;
    if (id == 1) return g_agg;
    if (id == 2) return g_agg + (size_t)N_NODES * DOUT;
    return g_agg + 2 * (size_t)N_NODES * DOUT;
}

// ---------------- CSR build ---------------------------------------------------
__global__ void k_zero_deg() {
    int i = blockIdx.x * blockDim.x + threadIdx.x;
    if (i < N_NODES) g_deg[i] = 0;
}

// edge_index is INT32 (JAX x64 disabled: "int64" request silently becomes int32)
__global__ void k_deg(const int* __restrict__ ei) {
    int e = blockIdx.x * blockDim.x + threadIdx.x;
    if (e < N_EDGES) atomicAdd(&g_deg[ei[N_EDGES + e]], 1);
}

__device__ __forceinline__ int warp_iscan(int v, int lane) {
#pragma unroll
    for (int off = 1; off < 32; off <<= 1) {
        int t = __shfl_up_sync(~0u, v, off);
        if (lane >= off) v += t;
    }
    return v;
}

// single block, 1024 threads: exclusive scan of g_deg -> g_rowptr/g_cur, plus inv
__global__ __launch_bounds__(1024) void k_scan() {
    __shared__ int wsum[32];
    __shared__ int s_carry;
    const int tid  = threadIdx.x;
    const int lane = tid & 31;
    const int wid  = tid >> 5;
    if (tid == 0) s_carry = 0;
    __syncthreads();
    for (int base = 0; base < N_NODES; base += 1024) {
        int i = base + tid;
        int v = (i < N_NODES) ? g_deg[i] : 0;
        int incl = warp_iscan(v, lane);
        if (lane == 31) wsum[wid] = incl;
        __syncthreads();
        if (wid == 0) {
            int s = wsum[lane];
            s = warp_iscan(s, lane);
            wsum[lane] = s;
        }
        __syncthreads();
        int wexcl = (wid > 0) ? wsum[wid - 1] : 0;
        int excl  = s_carry + wexcl + (incl - v);
        if (i < N_NODES) {
            g_rowptr[i] = excl;
            g_cur[i]    = excl;
            g_inv[i]    = 1.0f / fmaxf((float)v, 1.0f);
        }
        __syncthreads();                       // all reads of s_carry/wsum done
        if (tid == 0) s_carry += wsum[31];
        __syncthreads();
    }
    if (tid == 0) g_rowptr[N_NODES] = s_carry;
}

__global__ void k_fill(const int* __restrict__ ei) {
    int e = blockIdx.x * blockDim.x + threadIdx.x;
    if (e >= N_EDGES) return;
    int s = ei[e];
    int d = ei[N_EDGES + e];
    int pos = atomicAdd(&g_cur[d], 1);
    g_eidx[pos] = s;
}

// ---------------- SGEMM, K fixed = 128 ---------------------------------------
// C[M,Ncols] = A[M,128] @ B[128,Ncols] (+bias) (+epilogue)
// BM=128, BK=16, TM=TN=8. A_SEL=-1 -> A from param; else sel(A_SEL).
// EPI: 0 -> C = acc (+bias)
//      1 -> C = relu(acc + bias + agg[row,col]*inv[row])   (Ncols must be D)
template <int BN, int THREADS, int A_SEL, int C_SEL, int EPI>
__global__ __launch_bounds__(THREADS) void sgemm_k128(
    const float* __restrict__ Aparam, const float* __restrict__ B,
    const float* __restrict__ bias, int M, int Ncols)
{
    constexpr int BM = 128, BK = 16, TM = 8, TN = 8;
    __shared__ float As[BK][BM + 4];
    __shared__ float Bs[BK][BN];

    const float* A = (A_SEL < 0) ? Aparam : sel(A_SEL);
    float*       C = sel(C_SEL);

    const int tid     = threadIdx.x;
    const int rowBase = blockIdx.x * BM;
    const int tcol    = tid % (BN / TN);
    const int trow    = tid / (BN / TN);

    float acc[TM][TN];
#pragma unroll
    for (int i = 0; i < TM; i++)
#pragma unroll
        for (int j = 0; j < TN; j++) acc[i][j] = 0.f;

    for (int kt = 0; kt < D / BK; kt++) {
        for (int i = tid; i < BM * BK / 4; i += THREADS) {
            int am = i / (BK / 4);
            int ak = (i % (BK / 4)) * 4;
            float4 v = make_float4(0.f, 0.f, 0.f, 0.f);
            int row = rowBase + am;
            if (row < M)
                v = *(const float4*)(A + (size_t)row * D + kt * BK + ak);
            As[ak + 0][am] = v.x; As[ak + 1][am] = v.y;
            As[ak + 2][am] = v.z; As[ak + 3][am] = v.w;
        }
        for (int i = tid; i < BK * BN; i += THREADS) {
            int bk = i / BN, bj = i % BN;
            Bs[bk][bj] = (bj < Ncols) ? B[(size_t)(kt * BK + bk) * Ncols + bj] : 0.f;
        }
        __syncthreads();
#pragma unroll
        for (int k = 0; k < BK; k++) {
            float ra[TM], rb[TN];
#pragma unroll
            for (int i = 0; i < TM; i++) ra[i] = As[k][trow * TM + i];
#pragma unroll
            for (int j = 0; j < TN; j++) rb[j] = Bs[k][tcol * TN + j];
#pragma unroll
            for (int i = 0; i < TM; i++)
#pragma unroll
                for (int j = 0; j < TN; j++) acc[i][j] += ra[i] * rb[j];
        }
        __syncthreads();
    }

#pragma unroll
    for (int i = 0; i < TM; i++) {
        int row = rowBase + trow * TM + i;
        if (row >= M) continue;
        float inv = (EPI == 1) ? g_inv[row] : 0.f;
#pragma unroll
        for (int j = 0; j < TN; j++) {
            int col = tcol * TN + j;
            if (col >= Ncols) continue;
            float r = acc[i][j] + (bias ? bias[col] : 0.f);
            if (EPI == 1)
                r = fmaxf(fmaf(g_agg[(size_t)row * D + col], inv, r), 0.f);
            C[(size_t)row * Ncols + col] = r;
        }
    }
}

// ---------------- gather layer 1: warp per node, 128 floats = 32 x float4 -----
__device__ __forceinline__ void add4(float4& a, const float4 b) {
    a.x += b.x; a.y += b.y; a.z += b.z; a.w += b.w;
}

__global__ void k_gather128() {
    int node = (blockIdx.x * blockDim.x + threadIdx.x) >> 5;
    int lane = threadIdx.x & 31;
    if (node >= N_NODES) return;
    int beg = g_rowptr[node];
    int end = g_rowptr[node + 1];
    const float4* zz = (const float4*)g_z;
    float4 acc = make_float4(0.f, 0.f, 0.f, 0.f);
    int j = beg;
    for (; j + 3 < end; j += 4) {
        int s0 = g_eidx[j], s1 = g_eidx[j + 1];
        int s2 = g_eidx[j + 2], s3 = g_eidx[j + 3];
        float4 a = zz[(size_t)s0 * 32 + lane];
        float4 b = zz[(size_t)s1 * 32 + lane];
        float4 c = zz[(size_t)s2 * 32 + lane];
        float4 d = zz[(size_t)s3 * 32 + lane];
        add4(acc, a); add4(acc, b); add4(acc, c); add4(acc, d);
    }
    for (; j < end; j++)
        add4(acc, zz[(size_t)g_eidx[j] * 32 + lane]);
    ((float4*)g_agg)[(size_t)node * 32 + lane] = acc;
}

// ---------------- gather layer 2: warp per node, 40 floats = 10 x float4 ------
__global__ void k_gather40() {
    int node = (blockIdx.x * blockDim.x + threadIdx.x) >> 5;
    int lane = threadIdx.x & 31;
    if (node >= N_NODES || lane >= DOUT / 4) return;
    int beg = g_rowptr[node];
    int end = g_rowptr[node + 1];
    const float* u = sel(1);
    float4 acc = make_float4(0.f, 0.f, 0.f, 0.f);
    int j = beg;
    for (; j + 3 < end; j += 4) {
        int s0 = g_eidx[j], s1 = g_eidx[j + 1];
        int s2 = g_eidx[j + 2], s3 = g_eidx[j + 3];
        float4 a = ((const float4*)(u + (size_t)s0 * DOUT))[lane];
        float4 b = ((const float4*)(u + (size_t)s1 * DOUT))[lane];
        float4 c = ((const float4*)(u + (size_t)s2 * DOUT))[lane];
        float4 d = ((const float4*)(u + (size_t)s3 * DOUT))[lane];
        add4(acc, a); add4(acc, b); add4(acc, c); add4(acc, d);
    }
    for (; j < end; j++)
        add4(acc, ((const float4*)(u + (size_t)g_eidx[j] * DOUT))[lane]);
    ((float4*)(sel(3) + (size_t)node * DOUT))[lane] = acc;
}

// ---------------- final: combine + log_softmax, one warp per row --------------
__global__ void k_out(float* __restrict__ out) {
    int warp = (blockIdx.x * blockDim.x + threadIdx.x) >> 5;
    int lane = threadIdx.x & 31;
    if (warp >= N_NODES) return;
    float inv = g_inv[warp];
    const float* a = sel(3) + (size_t)warp * DOUT;  // ag2
    const float* v = sel(2) + (size_t)warp * DOUT;  // v = h@W2_r + b2
    float x0 = fmaf(a[lane], inv, v[lane]);
    float x1 = (lane < DOUT - 32) ? fmaf(a[32 + lane], inv, v[32 + lane])
                                  : -INFINITY;
    float m = fmaxf(x0, x1);
#pragma unroll
    for (int o = 16; o; o >>= 1) m = fmaxf(m, __shfl_xor_sync(~0u, m, o));
    float s = expf(x0 - m) + ((lane < DOUT - 32) ? expf(x1 - m) : 0.f);
#pragma unroll
    for (int o = 16; o; o >>= 1) s += __shfl_xor_sync(~0u, s, o);
    float lse = m + logf(s);
    out[(size_t)warp * DOUT + lane] = x0 - lse;
    if (lane < DOUT - 32) out[(size_t)warp * DOUT + 32 + lane] = x1 - lse;
}

// ---------------- launch: kernel launches ONLY (graph-capture safe) -----------
extern "C" void kernel_launch(void* const* d_in, const int* in_sizes, int n_in,
                              void* d_out, int out_size) {
    const float* x   = (const float*)d_in[0];
    const int*   ei  = (const int*)d_in[1];   // int32! (JAX default: no x64)
    const float* W1l = (const float*)d_in[2];
    const float* W1r = (const float*)d_in[3];
    const float* b1  = (const float*)d_in[4];
    const float* W2l = (const float*)d_in[5];
    const float* W2r = (const float*)d_in[6];
    const float* b2  = (const float*)d_in[7];
    float* out = (float*)d_out;

    const int gb = (N_NODES + 127) / 128;              // 782 row-blocks
    const int ge = (N_EDGES + 255) / 256;              // edge-parallel grid
    const int gw = (N_NODES * 32 + 255) / 256;         // warp-per-node grid

    // CSR build (int atomics only)
    k_zero_deg<<<(N_NODES + 255) / 256, 256>>>();
    k_deg <<<ge, 256>>>(ei);
    k_scan<<<1, 1024>>>();
    k_fill<<<ge, 256>>>(ei);

    // layer 1
    // z = x @ W1_l -> g_z
    sgemm_k128<128, 256, -1, 0, 0><<<gb, 256>>>(x, W1l, nullptr, N_NODES, D);
    // agg[d] = sum_{s in N(d)} z[s]   (deterministic CSR gather)
    k_gather128<<<gw, 256>>>();
    // h = relu(x @ W1_r + b1 + agg*inv) -> g_z (fused epilogue)
    sgemm_k128<128, 256, -1, 0, 1><<<gb, 256>>>(x, W1r, b1, N_NODES, D);

    // layer 2 (aggregate AFTER the 128->40 projection: 3.2x less gather traffic)
    // u = h @ W2_l -> sel(1)
    sgemm_k128<64, 128, 0, 1, 0><<<gb, 128>>>(nullptr, W2l, nullptr, N_NODES, DOUT);
    // v = h @ W2_r + b2 -> sel(2)
    sgemm_k128<64, 128, 0, 2, 0><<<gb, 128>>>(nullptr, W2r, b2, N_NODES, DOUT);
    // ag2[d] = sum u[s]
    k_gather40<<<gw, 256>>>();

    // out = log_softmax(ag2*inv + v)
    k_out<<<gw, 256>>>(out);
}

// round 13
// speedup vs baseline: 1.2378x; 1.2332x over previous
#include <cuda_runtime.h>
#include <math.h>

#define N_NODES 100000
#define N_EDGES 3200000
#define D       128
#define DOUT    40

#define SCAN_BLKS ((N_NODES + 1023) / 1024)   // 98

// ---------------- scratch (device globals; referenced ONLY from device code) --
__device__ float g_z  [(size_t)N_NODES * D];   // z = x@W1_l, then h
__device__ float g_agg[(size_t)N_NODES * D];   // agg (layer1); later u | v
__device__ float g_inv[N_NODES];
__device__ int   g_deg[N_NODES];
__device__ int   g_rowptr[N_NODES + 1];
__device__ int   g_cur[N_NODES];
__device__ int   g_eidx[N_EDGES];
__device__ int   g_bsum[128];
__device__ int   g_boff[128];

// 0: g_z (z/h)  1: u region  2: v region
__device__ __forceinline__ float* sel(int id) {
    if (id == 0) return g_z;
    if (id == 1) return g_agg;
    return g_agg + (size_t)N_NODES * DOUT;
}

// ---------------- CSR build ---------------------------------------------------
__global__ void k_zero_deg() {
    int i = blockIdx.x * blockDim.x + threadIdx.x;
    if (i < N_NODES) g_deg[i] = 0;
}

__global__ void k_deg(const int* __restrict__ ei) {
    int e = blockIdx.x * blockDim.x + threadIdx.x;
    if (e < N_EDGES) atomicAdd(&g_deg[ei[N_EDGES + e]], 1);
}

__device__ __forceinline__ int warp_iscan(int v, int lane) {
#pragma unroll
    for (int off = 1; off < 32; off <<= 1) {
        int t = __shfl_up_sync(~0u, v, off);
        if (lane >= off) v += t;
    }
    return v;
}

// S1: per-block (1024 nodes) sum of degrees -> g_bsum[b]
__global__ __launch_bounds__(256) void k_s1() {
    __shared__ int wsum[8];
    int t = threadIdx.x, lane = t & 31, wid = t >> 5;
    int i0 = blockIdx.x * 1024 + t * 4;
    int s = 0;
#pragma unroll
    for (int k = 0; k < 4; k++) {
        int i = i0 + k;
        if (i < N_NODES) s += g_deg[i];
    }
#pragma unroll
    for (int o = 16; o; o >>= 1) s += __shfl_xor_sync(~0u, s, o);
    if (lane == 0) wsum[wid] = s;
    __syncthreads();
    if (wid == 0) {
        int v = (lane < 8) ? wsum[lane] : 0;
#pragma unroll
        for (int o = 4; o; o >>= 1) v += __shfl_xor_sync(~0u, v, o);
        if (t == 0) g_bsum[blockIdx.x] = v;
    }
}

// S2: exclusive scan of the block sums -> g_boff
__global__ __launch_bounds__(128) void k_s2() {
    __shared__ int wsum[4];
    int t = threadIdx.x, lane = t & 31, wid = t >> 5;
    int v = (t < SCAN_BLKS) ? g_bsum[t] : 0;
    int incl = warp_iscan(v, lane);
    if (lane == 31) wsum[wid] = incl;
    __syncthreads();
    if (wid == 0) {
        int s = (lane < 4) ? wsum[lane] : 0;
        s = warp_iscan(s, lane);
        if (lane < 4) wsum[lane] = s;
    }
    __syncthreads();
    int excl = incl - v + (wid ? wsum[wid - 1] : 0);
    if (t < SCAN_BLKS) g_boff[t] = excl;
    if (t == 0) g_rowptr[N_NODES] = N_EDGES;
}

// S3: block-local exclusive scan + block offset -> rowptr/cur/inv
__global__ __launch_bounds__(256) void k_s3() {
    __shared__ int wsum[8];
    int t = threadIdx.x, lane = t & 31, wid = t >> 5;
    int i0 = blockIdx.x * 1024 + t * 4;
    int d[4];
    int ts = 0;
#pragma unroll
    for (int k = 0; k < 4; k++) {
        int i = i0 + k;
        d[k] = (i < N_NODES) ? g_deg[i] : 0;
        ts += d[k];
    }
    int incl = warp_iscan(ts, lane);
    if (lane == 31) wsum[wid] = incl;
    __syncthreads();
    if (wid == 0) {
        int s = (lane < 8) ? wsum[lane] : 0;
        s = warp_iscan(s, lane);
        if (lane < 8) wsum[lane] = s;
    }
    __syncthreads();
    int base = g_boff[blockIdx.x] + incl - ts + (wid ? wsum[wid - 1] : 0);
#pragma unroll
    for (int k = 0; k < 4; k++) {
        int i = i0 + k;
        if (i < N_NODES) {
            g_rowptr[i] = base;
            g_cur[i]    = base;
            g_inv[i]    = 1.0f / fmaxf((float)d[k], 1.0f);
        }
        base += d[k];
    }
}

__global__ void k_fill(const int* __restrict__ ei) {
    int e = blockIdx.x * blockDim.x + threadIdx.x;
    if (e >= N_EDGES) return;
    int s = ei[e];
    int dd = ei[N_EDGES + e];
    int pos = atomicAdd(&g_cur[dd], 1);
    g_eidx[pos] = s;
}

// ---------------- SGEMM 128-wide, double-buffered -----------------------------
// sel(0)[M,128] = A[M,128] @ B[128,128] (+bias) (+EPI)
// EPI: 0 -> C = acc (+bias); 1 -> C = relu(acc + bias + g_agg[row,col]*inv[row])
template <int EPI>
__global__ __launch_bounds__(256) void sgemm_k128(
    const float* __restrict__ A, const float* __restrict__ B,
    const float* __restrict__ bias, int M)
{
    constexpr int BM = 128, BN = 128, BK = 16, TM = 8, TN = 8, THREADS = 256;
    __shared__ float As[2][BK][BM + 4];
    __shared__ float Bs[2][BK][BN];

    float* C = sel(0);

    const int tid     = threadIdx.x;
    const int rowBase = blockIdx.x * BM;
    const int tcol    = tid % (BN / TN);
    const int trow    = tid / (BN / TN);

    float4 pa[2], pb[2];

    auto load_stage = [&](int kt) {
#pragma unroll
        for (int s = 0; s < 2; s++) {
            int i  = tid + s * THREADS;
            int am = i / (BK / 4);
            int ak = (i % (BK / 4)) * 4;
            int row = rowBase + am;
            pa[s] = (row < M)
                ? *(const float4*)(A + (size_t)row * D + kt * BK + ak)
                : make_float4(0.f, 0.f, 0.f, 0.f);
            int bk = i / (BN / 4);
            int b4 = i % (BN / 4);
            pb[s] = *(const float4*)(B + (size_t)(kt * BK + bk) * BN + b4 * 4);
        }
    };
    auto store_stage = [&](int buf) {
#pragma unroll
        for (int s = 0; s < 2; s++) {
            int i  = tid + s * THREADS;
            int am = i / (BK / 4);
            int ak = (i % (BK / 4)) * 4;
            As[buf][ak + 0][am] = pa[s].x; As[buf][ak + 1][am] = pa[s].y;
            As[buf][ak + 2][am] = pa[s].z; As[buf][ak + 3][am] = pa[s].w;
            int bk = i / (BN / 4);
            int b4 = i % (BN / 4);
            ((float4*)Bs[buf][bk])[b4] = pb[s];
        }
    };

    float acc[TM][TN];
#pragma unroll
    for (int i = 0; i < TM; i++)
#pragma unroll
        for (int j = 0; j < TN; j++) acc[i][j] = 0.f;

    load_stage(0);
    store_stage(0);

    constexpr int NKT = D / BK;  // 8
#pragma unroll
    for (int kt = 0; kt < NKT; kt++) {
        __syncthreads();
        int buf = kt & 1;
        if (kt < NKT - 1) load_stage(kt + 1);
#pragma unroll
        for (int k = 0; k < BK; k++) {
            float ra[TM], rb[TN];
#pragma unroll
            for (int i = 0; i < TM; i++) ra[i] = As[buf][k][trow * TM + i];
#pragma unroll
            for (int j = 0; j < TN; j++) rb[j] = Bs[buf][k][tcol * TN + j];
#pragma unroll
            for (int i = 0; i < TM; i++)
#pragma unroll
                for (int j = 0; j < TN; j++) acc[i][j] += ra[i] * rb[j];
        }
        if (kt < NKT - 1) store_stage(buf ^ 1);
    }

#pragma unroll
    for (int i = 0; i < TM; i++) {
        int row = rowBase + trow * TM + i;
        if (row >= M) continue;
        float inv = (EPI == 1) ? g_inv[row] : 0.f;
#pragma unroll
        for (int j = 0; j < TN; j++) {
            int col = tcol * TN + j;
            float r = acc[i][j] + (bias ? bias[col] : 0.f);
            if (EPI == 1)
                r = fmaxf(fmaf(g_agg[(size_t)row * D + col], inv, r), 0.f);
            C[(size_t)row * D + col] = r;
        }
    }
}

// ---------------- merged layer-2 GEMM: [u | v] = h @ [W2l | W2r] (+b2 on v) ---
// BM=128, BN=80 (40+40), BK=16, TM=8, TN=5, 256 threads, double-buffered.
__global__ __launch_bounds__(256) void sgemm2(
    const float* __restrict__ W2l, const float* __restrict__ W2r,
    const float* __restrict__ b2, int M)
{
    constexpr int BM = 128, BN = 80, BK = 16, TM = 8, TN = 5, THREADS = 256;
    __shared__ float As[2][BK][BM + 4];
    __shared__ float Bs[2][BK][BN];

    const float* A = sel(0);   // h
    float* U = sel(1);
    float* V = sel(2);

    const int tid     = threadIdx.x;
    const int rowBase = blockIdx.x * BM;
    const int tcol    = tid % (BN / TN);   // 16
    const int trow    = tid / (BN / TN);   // 16

    float4 pa[2];
    float  pb[5];

    auto load_stage = [&](int kt) {
#pragma unroll
        for (int s = 0; s < 2; s++) {
            int i  = tid + s * THREADS;
            int am = i / (BK / 4);
            int ak = (i % (BK / 4)) * 4;
            int row = rowBase + am;
            pa[s] = (row < M)
                ? *(const float4*)(A + (size_t)row * D + kt * BK + ak)
                : make_float4(0.f, 0.f, 0.f, 0.f);
        }
#pragma unroll
        for (int s = 0; s < 5; s++) {
            int j  = tid + s * THREADS;     // BK*BN = 1280 scalars
            int bk = j / BN;
            int bj = j % BN;
            int krow = kt * BK + bk;
            pb[s] = (bj < DOUT) ? W2l[(size_t)krow * DOUT + bj]
                                : W2r[(size_t)krow * DOUT + (bj - DOUT)];
        }
    };
    auto store_stage = [&](int buf) {
#pragma unroll
        for (int s = 0; s < 2; s++) {
            int i  = tid + s * THREADS;
            int am = i / (BK / 4);
            int ak = (i % (BK / 4)) * 4;
            As[buf][ak + 0][am] = pa[s].x; As[buf][ak + 1][am] = pa[s].y;
            As[buf][ak + 2][am] = pa[s].z; As[buf][ak + 3][am] = pa[s].w;
        }
#pragma unroll
        for (int s = 0; s < 5; s++) {
            int j = tid + s * THREADS;
            Bs[buf][j / BN][j % BN] = pb[s];
        }
    };

    float acc[TM][TN];
#pragma unroll
    for (int i = 0; i < TM; i++)
#pragma unroll
        for (int j = 0; j < TN; j++) acc[i][j] = 0.f;

    load_stage(0);
    store_stage(0);

    constexpr int NKT = D / BK;
#pragma unroll
    for (int kt = 0; kt < NKT; kt++) {
        __syncthreads();
        int buf = kt & 1;
        if (kt < NKT - 1) load_stage(kt + 1);
#pragma unroll
        for (int k = 0; k < BK; k++) {
            float ra[TM], rb[TN];
#pragma unroll
            for (int i = 0; i < TM; i++) ra[i] = As[buf][k][trow * TM + i];
#pragma unroll
            for (int j = 0; j < TN; j++) rb[j] = Bs[buf][k][tcol * TN + j];
#pragma unroll
            for (int i = 0; i < TM; i++)
#pragma unroll
                for (int j = 0; j < TN; j++) acc[i][j] += ra[i] * rb[j];
        }
        if (kt < NKT - 1) store_stage(buf ^ 1);
    }

    // tcol 0..7 -> u cols 0..39 ; tcol 8..15 -> v cols 0..39 (+b2)
#pragma unroll
    for (int i = 0; i < TM; i++) {
        int row = rowBase + trow * TM + i;
        if (row >= M) continue;
#pragma unroll
        for (int j = 0; j < TN; j++) {
            int c = tcol * TN + j;
            if (c < DOUT)
                U[(size_t)row * DOUT + c] = acc[i][j];
            else
                V[(size_t)row * DOUT + (c - DOUT)] = acc[i][j] + b2[c - DOUT];
        }
    }
}

// ---------------- gather layer 1: warp per node, 128 floats = 32 x float4 -----
__device__ __forceinline__ void add4(float4& a, const float4 b) {
    a.x += b.x; a.y += b.y; a.z += b.z; a.w += b.w;
}

__global__ void k_gather128() {
    int node = (blockIdx.x * blockDim.x + threadIdx.x) >> 5;
    int lane = threadIdx.x & 31;
    if (node >= N_NODES) return;
    int beg = g_rowptr[node];
    int end = g_rowptr[node + 1];
    const float4* zz = (const float4*)g_z;
    float4 acc = make_float4(0.f, 0.f, 0.f, 0.f);
    int j = beg;
    for (; j + 3 < end; j += 4) {
        int s0 = g_eidx[j], s1 = g_eidx[j + 1];
        int s2 = g_eidx[j + 2], s3 = g_eidx[j + 3];
        float4 a = zz[(size_t)s0 * 32 + lane];
        float4 b = zz[(size_t)s1 * 32 + lane];
        float4 c = zz[(size_t)s2 * 32 + lane];
        float4 d = zz[(size_t)s3 * 32 + lane];
        add4(acc, a); add4(acc, b); add4(acc, c); add4(acc, d);
    }
    for (; j < end; j++)
        add4(acc, zz[(size_t)g_eidx[j] * 32 + lane]);
    ((float4*)g_agg)[(size_t)node * 32 + lane] = acc;
}

// ---------------- gather layer 2 + log_softmax, fused (warp per node) ---------
__global__ void k_gather_out(float* __restrict__ out) {
    int node = (blockIdx.x * blockDim.x + threadIdx.x) >> 5;
    int lane = threadIdx.x & 31;
    if (node >= N_NODES) return;
    const bool act = (lane < DOUT / 4);   // lanes 0..9 own 4 cols each
    int beg = g_rowptr[node];
    int end = g_rowptr[node + 1];
    const float* u = sel(1);
    float4 acc = make_float4(0.f, 0.f, 0.f, 0.f);
    int j = beg;
    for (; j + 3 < end; j += 4) {
        int s0 = g_eidx[j], s1 = g_eidx[j + 1];
        int s2 = g_eidx[j + 2], s3 = g_eidx[j + 3];
        if (act) {
            float4 a = ((const float4*)(u + (size_t)s0 * DOUT))[lane];
            float4 b = ((const float4*)(u + (size_t)s1 * DOUT))[lane];
            float4 c = ((const float4*)(u + (size_t)s2 * DOUT))[lane];
            float4 d = ((const float4*)(u + (size_t)s3 * DOUT))[lane];
            add4(acc, a); add4(acc, b); add4(acc, c); add4(acc, d);
        }
    }
    for (; j < end; j++)
        if (act)
            add4(acc, ((const float4*)(u + (size_t)g_eidx[j] * DOUT))[lane]);

    float inv = g_inv[node];
    float4 x = make_float4(0.f, 0.f, 0.f, 0.f);
    if (act) {
        float4 v = ((const float4*)(sel(2) + (size_t)node * DOUT))[lane];
        x.x = fmaf(acc.x, inv, v.x);
        x.y = fmaf(acc.y, inv, v.y);
        x.z = fmaf(acc.z, inv, v.z);
        x.w = fmaf(acc.w, inv, v.w);
    }
    float m = act ? fmaxf(fmaxf(x.x, x.y), fmaxf(x.z, x.w)) : -INFINITY;
#pragma unroll
    for (int o = 16; o; o >>= 1) m = fmaxf(m, __shfl_xor_sync(~0u, m, o));
    float s = act ? (expf(x.x - m) + expf(x.y - m) + expf(x.z - m) + expf(x.w - m))
                  : 0.f;
#pragma unroll
    for (int o = 16; o; o >>= 1) s += __shfl_xor_sync(~0u, s, o);
    float lse = m + logf(s);
    if (act) {
        float4 r = make_float4(x.x - lse, x.y - lse, x.z - lse, x.w - lse);
        ((float4*)(out + (size_t)node * DOUT))[lane] = r;
    }
}

// ---------------- launch: kernel launches ONLY (graph-capture safe) -----------
extern "C" void kernel_launch(void* const* d_in, const int* in_sizes, int n_in,
                              void* d_out, int out_size) {
    const float* x   = (const float*)d_in[0];
    const int*   ei  = (const int*)d_in[1];   // int32 (JAX default: no x64)
    const float* W1l = (const float*)d_in[2];
    const float* W1r = (const float*)d_in[3];
    const float* b1  = (const float*)d_in[4];
    const float* W2l = (const float*)d_in[5];
    const float* W2r = (const float*)d_in[6];
    const float* b2  = (const float*)d_in[7];
    float* out = (float*)d_out;

    const int gb = (N_NODES + 127) / 128;       // 782 row-blocks
    const int ge = (N_EDGES + 255) / 256;
    const int gw = (N_NODES * 32 + 255) / 256;  // warp-per-node grid

    // CSR build (multi-block deterministic scan)
    k_zero_deg<<<(N_NODES + 255) / 256, 256>>>();
    k_deg<<<ge, 256>>>(ei);
    k_s1<<<SCAN_BLKS, 256>>>();
    k_s2<<<1, 128>>>();
    k_s3<<<SCAN_BLKS, 256>>>();
    k_fill<<<ge, 256>>>(ei);

    // layer 1: z = x@W1l -> g_z ; agg = gather(z) ; h = relu(x@W1r+b1+agg*inv) -> g_z
    sgemm_k128<0><<<gb, 256>>>(x, W1l, nullptr, N_NODES);
    k_gather128<<<gw, 256>>>();
    sgemm_k128<1><<<gb, 256>>>(x, W1r, b1, N_NODES);

    // layer 2: [u|v] = h @ [W2l|W2r] (+b2 on v), then fused gather+log_softmax
    sgemm2<<<gb, 256>>>(W2l, W2r, b2, N_NODES);
    k_gather_out<<<gw, 256>>>(out);
}

// round 15
// speedup vs baseline: 1.5511x; 1.2531x over previous
#include <cuda_runtime.h>
#include <cuda_bf16.h>
#include <math.h>
#include <cstdint>

#define N_NODES 100000
#define N_EDGES 3200000
#define D       128
#define DOUT    40

#define SCAN_BLKS ((N_NODES + 1023) / 1024)   // 98

// ---------------- scratch (device globals; referenced ONLY from device code) --
__device__ float g_z  [(size_t)N_NODES * D];   // z = x@W1_l, then h
__device__ float g_agg[(size_t)N_NODES * D];   // agg (layer1); later u | v
__device__ float g_inv[N_NODES];
__device__ int   g_deg[N_NODES];
__device__ int   g_rowptr[N_NODES + 1];
__device__ int   g_cur[N_NODES];
__device__ int   g_eidx[N_EDGES];
__device__ int   g_bsum[128];
__device__ int   g_boff[128];
// bf16 hi/lo split images
__device__ __nv_bfloat16 g_xhi[(size_t)N_NODES * D];
__device__ __nv_bfloat16 g_xlo[(size_t)N_NODES * D];
// W images: [mat(2)][part hi/lo(2)][n(128)][k(128)] bf16, k-contiguous
__device__ __nv_bfloat16 g_wt[2 * 2 * 128 * 128];

// 0: g_z (z/h)  1: u region  2: v region
__device__ __forceinline__ float* sel(int id) {
    if (id == 0) return g_z;
    if (id == 1) return g_agg;
    return g_agg + (size_t)N_NODES * DOUT;
}

// ---------------- CSR build ---------------------------------------------------
__global__ void k_zero_deg() {
    int i = blockIdx.x * blockDim.x + threadIdx.x;
    if (i < N_NODES) g_deg[i] = 0;
}

__global__ void k_deg(const int* __restrict__ ei) {
    int e = blockIdx.x * blockDim.x + threadIdx.x;
    if (e < N_EDGES) atomicAdd(&g_deg[ei[N_EDGES + e]], 1);
}

__device__ __forceinline__ int warp_iscan(int v, int lane) {
#pragma unroll
    for (int off = 1; off < 32; off <<= 1) {
        int t = __shfl_up_sync(~0u, v, off);
        if (lane >= off) v += t;
    }
    return v;
}

__global__ __launch_bounds__(256) void k_s1() {
    __shared__ int wsum[8];
    int t = threadIdx.x, lane = t & 31, wid = t >> 5;
    int i0 = blockIdx.x * 1024 + t * 4;
    int s = 0;
#pragma unroll
    for (int k = 0; k < 4; k++) {
        int i = i0 + k;
        if (i < N_NODES) s += g_deg[i];
    }
#pragma unroll
    for (int o = 16; o; o >>= 1) s += __shfl_xor_sync(~0u, s, o);
    if (lane == 0) wsum[wid] = s;
    __syncthreads();
    if (wid == 0) {
        int v = (lane < 8) ? wsum[lane] : 0;
#pragma unroll
        for (int o = 4; o; o >>= 1) v += __shfl_xor_sync(~0u, v, o);
        if (t == 0) g_bsum[blockIdx.x] = v;
    }
}

__global__ __launch_bounds__(128) void k_s2() {
    __shared__ int wsum[4];
    int t = threadIdx.x, lane = t & 31, wid = t >> 5;
    int v = (t < SCAN_BLKS) ? g_bsum[t] : 0;
    int incl = warp_iscan(v, lane);
    if (lane == 31) wsum[wid] = incl;
    __syncthreads();
    if (wid == 0) {
        int s = (lane < 4) ? wsum[lane] : 0;
        s = warp_iscan(s, lane);
        if (lane < 4) wsum[lane] = s;
    }
    __syncthreads();
    int excl = incl - v + (wid ? wsum[wid - 1] : 0);
    if (t < SCAN_BLKS) g_boff[t] = excl;
    if (t == 0) g_rowptr[N_NODES] = N_EDGES;
}

__global__ __launch_bounds__(256) void k_s3() {
    __shared__ int wsum[8];
    int t = threadIdx.x, lane = t & 31, wid = t >> 5;
    int i0 = blockIdx.x * 1024 + t * 4;
    int d[4];
    int ts = 0;
#pragma unroll
    for (int k = 0; k < 4; k++) {
        int i = i0 + k;
        d[k] = (i < N_NODES) ? g_deg[i] : 0;
        ts += d[k];
    }
    int incl = warp_iscan(ts, lane);
    if (lane == 31) wsum[wid] = incl;
    __syncthreads();
    if (wid == 0) {
        int s = (lane < 8) ? wsum[lane] : 0;
        s = warp_iscan(s, lane);
        if (lane < 8) wsum[lane] = s;
    }
    __syncthreads();
    int base = g_boff[blockIdx.x] + incl - ts + (wid ? wsum[wid - 1] : 0);
#pragma unroll
    for (int k = 0; k < 4; k++) {
        int i = i0 + k;
        if (i < N_NODES) {
            g_rowptr[i] = base;
            g_cur[i]    = base;
            g_inv[i]    = 1.0f / fmaxf((float)d[k], 1.0f);
        }
        base += d[k];
    }
}

__global__ void k_fill(const int* __restrict__ ei) {
    int e = blockIdx.x * blockDim.x + threadIdx.x;
    if (e >= N_EDGES) return;
    int s = ei[e];
    int dd = ei[N_EDGES + e];
    int pos = atomicAdd(&g_cur[dd], 1);
    g_eidx[pos] = s;
}

// ---------------- bf16 hi/lo prep ---------------------------------------------
// x -> g_xhi/g_xlo (row-major [row][k], bf16x2-packed pairs)
__global__ void k_prepx(const float* __restrict__ x) {
    size_t i = (size_t)blockIdx.x * blockDim.x + threadIdx.x;   // pair index
    if (i >= (size_t)N_NODES * D / 2) return;
    float2 f = ((const float2*)x)[i];
    __nv_bfloat162 h2 = __floats2bfloat162_rn(f.x, f.y);
    float2 hf = __bfloat1622float2(h2);
    __nv_bfloat162 l2 = __floats2bfloat162_rn(f.x - hf.x, f.y - hf.y);
    ((__nv_bfloat162*)g_xhi)[i] = h2;
    ((__nv_bfloat162*)g_xlo)[i] = l2;
}

// W (fp32 [k][n]) -> g_wt [mat][part][n][k] bf16
__global__ __launch_bounds__(256) void k_prepw(const float* __restrict__ W0,
                                               const float* __restrict__ W1)
{
    int mat = blockIdx.x;
    const float* W = mat ? W1 : W0;
    for (int idx = threadIdx.x; idx < 128 * 128; idx += 256) {
        int k = idx >> 7;
        int n = idx & 127;
        float v = W[(size_t)k * 128 + n];
        __nv_bfloat16 hb = __float2bfloat16(v);
        float hf = __bfloat162float(hb);
        __nv_bfloat16 lb = __float2bfloat16(v - hf);
        g_wt[((size_t)(mat * 2 + 0) * 128 + n) * 128 + k] = hb;
        g_wt[((size_t)(mat * 2 + 1) * 128 + n) * 128 + k] = lb;
    }
}

// ---------------- tensor-core GEMM via mma.sync (HMMA bf16, fp32 acc) ---------
// sel(0)[M,128] = x[M,128] @ W_mat[128,128], hi/lo 3-term compensation.
// grid (ceil(M/128), 2): blockIdx.y = 64-col output half. 256 threads, 8 warps.
// warp layout: wm = wid>>1 (32 rows), wn = wid&1 (32 cols); 2x4 m16n8k16 tiles.
// EPI: 0 -> C = acc (+bias); 1 -> C = relu(acc + bias + g_agg[row,col]*inv[row])
__device__ __forceinline__ void mma16816(float* c, const uint32_t* a,
                                         const uint32_t* b) {
    asm volatile(
        "mma.sync.aligned.m16n8k16.row.col.f32.bf16.bf16.f32 "
        "{%0,%1,%2,%3}, {%4,%5,%6,%7}, {%8,%9}, {%0,%1,%2,%3};"
        : "+f"(c[0]), "+f"(c[1]), "+f"(c[2]), "+f"(c[3])
        : "r"(a[0]), "r"(a[1]), "r"(a[2]), "r"(a[3]), "r"(b[0]), "r"(b[1]));
}

template <int EPI>
__global__ __launch_bounds__(256) void tmma(int mat, const float* __restrict__ bias,
                                            int M)
{
    constexpr int PAD = 40;                     // 80B row pitch: conflict-free frags
    __shared__ __align__(16) __nv_bfloat16 sA[2][128][PAD];
    __shared__ __align__(16) __nv_bfloat16 sB[2][64][PAD];

    const int tid  = threadIdx.x;
    const int wid  = tid >> 5;
    const int lane = tid & 31;
    const int wm   = wid >> 1;
    const int wn   = wid & 1;
    const int g    = lane >> 2;
    const int t4   = lane & 3;
    const int rowBase = blockIdx.x * 128;
    const int nh      = blockIdx.y;

    const __nv_bfloat16* Asrc[2] = { g_xhi, g_xlo };

    float acc[2][4][4];
#pragma unroll
    for (int mt = 0; mt < 2; mt++)
#pragma unroll
        for (int nt = 0; nt < 4; nt++)
#pragma unroll
            for (int q = 0; q < 4; q++) acc[mt][nt][q] = 0.f;

#pragma unroll
    for (int kc = 0; kc < 4; kc++) {           // K chunks of 32
        const int kb = kc * 32;
        if (kc) __syncthreads();               // protect smem reuse
        // A tile: 2 parts x 128 rows x 32 k  (1024 uint4)
        for (int i = tid; i < 1024; i += 256) {
            int part = i >> 9, j = i & 511;
            int r = j >> 2, c = j & 3;
            int row = rowBase + r;
            uint4 v = make_uint4(0, 0, 0, 0);
            if (row < M)
                v = *(const uint4*)(Asrc[part] + (size_t)row * D + kb + c * 8);
            *(uint4*)&sA[part][r][c * 8] = v;
        }
        // B tile: 2 parts x 64 n x 32 k  (512 uint4)
        for (int i = tid; i < 512; i += 256) {
            int part = i >> 8, j = i & 255;
            int r = j >> 2, c = j & 3;
            *(uint4*)&sB[part][r][c * 8] =
                *(const uint4*)(g_wt + ((size_t)(mat * 2 + part) * 128 + nh * 64 + r) * 128
                                + kb + c * 8);
        }
        __syncthreads();

#pragma unroll
        for (int ks = 0; ks < 2; ks++) {       // 2 k-steps of 16 per chunk
            const int k2 = ks * 16 + t4 * 2;
            uint32_t ah[2][4], al[2][4], bh[4][2], bl[4][2];
#pragma unroll
            for (int mt = 0; mt < 2; mt++) {
                int r = wm * 32 + mt * 16 + g;
                ah[mt][0] = *(const uint32_t*)&sA[0][r    ][k2];
                ah[mt][1] = *(const uint32_t*)&sA[0][r + 8][k2];
                ah[mt][2] = *(const uint32_t*)&sA[0][r    ][k2 + 8];
                ah[mt][3] = *(const uint32_t*)&sA[0][r + 8][k2 + 8];
                al[mt][0] = *(const uint32_t*)&sA[1][r    ][k2];
                al[mt][1] = *(const uint32_t*)&sA[1][r + 8][k2];
                al[mt][2] = *(const uint32_t*)&sA[1][r    ][k2 + 8];
                al[mt][3] = *(const uint32_t*)&sA[1][r + 8][k2 + 8];
            }
#pragma unroll
            for (int nt = 0; nt < 4; nt++) {
                int rn = wn * 32 + nt * 8 + g;
                bh[nt][0] = *(const uint32_t*)&sB[0][rn][k2];
                bh[nt][1] = *(const uint32_t*)&sB[0][rn][k2 + 8];
                bl[nt][0] = *(const uint32_t*)&sB[1][rn][k2];
                bl[nt][1] = *(const uint32_t*)&sB[1][rn][k2 + 8];
            }
#pragma unroll
            for (int mt = 0; mt < 2; mt++)
#pragma unroll
                for (int nt = 0; nt < 4; nt++) {
                    mma16816(acc[mt][nt], ah[mt], bh[nt]);   // hi*hi
                    mma16816(acc[mt][nt], al[mt], bh[nt]);   // lo*hi
                    mma16816(acc[mt][nt], ah[mt], bl[nt]);   // hi*lo
                }
        }
    }

    // epilogue: c0,c1 -> (row, col..col+1); c2,c3 -> (row+8, ...)
    float* C = sel(0);
#pragma unroll
    for (int mt = 0; mt < 2; mt++) {
        int r0 = rowBase + wm * 32 + mt * 16 + g;
#pragma unroll
        for (int half = 0; half < 2; half++) {
            int row = r0 + half * 8;
            if (row >= M) continue;
            float inv = (EPI == 1) ? g_inv[row] : 0.f;
#pragma unroll
            for (int nt = 0; nt < 4; nt++) {
                int col = nh * 64 + wn * 32 + nt * 8 + t4 * 2;
                float v0 = acc[mt][nt][half * 2 + 0];
                float v1 = acc[mt][nt][half * 2 + 1];
                if (bias) { v0 += bias[col]; v1 += bias[col + 1]; }
                if (EPI == 1) {
                    const float* ag = g_agg + (size_t)row * D + col;
                    v0 = fmaxf(fmaf(ag[0], inv, v0), 0.f);
                    v1 = fmaxf(fmaf(ag[1], inv, v1), 0.f);
                }
                *(float2*)(C + (size_t)row * D + col) = make_float2(v0, v1);
            }
        }
    }
}

// ---------------- merged layer-2 GEMM: [u | v] = h @ [W2l | W2r] (+b2 on v) ---
__global__ __launch_bounds__(256) void sgemm2(
    const float* __restrict__ W2l, const float* __restrict__ W2r,
    const float* __restrict__ b2, int M)
{
    constexpr int BM = 128, BN = 80, BK = 16, TM = 8, TN = 5, THREADS = 256;
    __shared__ float As[2][BK][BM + 4];
    __shared__ float Bs[2][BK][BN];

    const float* A = sel(0);   // h
    float* U = sel(1);
    float* V = sel(2);

    const int tid     = threadIdx.x;
    const int rowBase = blockIdx.x * BM;
    const int tcol    = tid % (BN / TN);   // 16
    const int trow    = tid / (BN / TN);   // 16

    float4 pa[2];
    float  pb[5];

    auto load_stage = [&](int kt) {
#pragma unroll
        for (int s = 0; s < 2; s++) {
            int i  = tid + s * THREADS;
            int am = i / (BK / 4);
            int ak = (i % (BK / 4)) * 4;
            int row = rowBase + am;
            pa[s] = (row < M)
                ? *(const float4*)(A + (size_t)row * D + kt * BK + ak)
                : make_float4(0.f, 0.f, 0.f, 0.f);
        }
#pragma unroll
        for (int s = 0; s < 5; s++) {
            int j  = tid + s * THREADS;
            int bk = j / BN;
            int bj = j % BN;
            int krow = kt * BK + bk;
            pb[s] = (bj < DOUT) ? W2l[(size_t)krow * DOUT + bj]
                                : W2r[(size_t)krow * DOUT + (bj - DOUT)];
        }
    };
    auto store_stage = [&](int buf) {
#pragma unroll
        for (int s = 0; s < 2; s++) {
            int i  = tid + s * THREADS;
            int am = i / (BK / 4);
            int ak = (i % (BK / 4)) * 4;
            As[buf][ak + 0][am] = pa[s].x; As[buf][ak + 1][am] = pa[s].y;
            As[buf][ak + 2][am] = pa[s].z; As[buf][ak + 3][am] = pa[s].w;
        }
#pragma unroll
        for (int s = 0; s < 5; s++) {
            int j = tid + s * THREADS;
            Bs[buf][j / BN][j % BN] = pb[s];
        }
    };

    float acc[TM][TN];
#pragma unroll
    for (int i = 0; i < TM; i++)
#pragma unroll
        for (int j = 0; j < TN; j++) acc[i][j] = 0.f;

    load_stage(0);
    store_stage(0);

    constexpr int NKT = D / BK;
#pragma unroll
    for (int kt = 0; kt < NKT; kt++) {
        __syncthreads();
        int buf = kt & 1;
        if (kt < NKT - 1) load_stage(kt + 1);
#pragma unroll
        for (int k = 0; k < BK; k++) {
            float ra[TM], rb[TN];
#pragma unroll
            for (int i = 0; i < TM; i++) ra[i] = As[buf][k][trow * TM + i];
#pragma unroll
            for (int j = 0; j < TN; j++) rb[j] = Bs[buf][k][tcol * TN + j];
#pragma unroll
            for (int i = 0; i < TM; i++)
#pragma unroll
                for (int j = 0; j < TN; j++) acc[i][j] += ra[i] * rb[j];
        }
        if (kt < NKT - 1) store_stage(buf ^ 1);
    }

#pragma unroll
    for (int i = 0; i < TM; i++) {
        int row = rowBase + trow * TM + i;
        if (row >= M) continue;
#pragma unroll
        for (int j = 0; j < TN; j++) {
            int c = tcol * TN + j;
            if (c < DOUT)
                U[(size_t)row * DOUT + c] = acc[i][j];
            else
                V[(size_t)row * DOUT + (c - DOUT)] = acc[i][j] + b2[c - DOUT];
        }
    }
}

// ---------------- gather layer 1: warp per node, 128 floats = 32 x float4 -----
__device__ __forceinline__ void add4(float4& a, const float4 b) {
    a.x += b.x; a.y += b.y; a.z += b.z; a.w += b.w;
}

__global__ void k_gather128() {
    int node = (blockIdx.x * blockDim.x + threadIdx.x) >> 5;
    int lane = threadIdx.x & 31;
    if (node >= N_NODES) return;
    int beg = g_rowptr[node];
    int end = g_rowptr[node + 1];
    const float4* zz = (const float4*)g_z;
    float4 acc = make_float4(0.f, 0.f, 0.f, 0.f);
    int j = beg;
    for (; j + 3 < end; j += 4) {
        int s0 = g_eidx[j], s1 = g_eidx[j + 1];
        int s2 = g_eidx[j + 2], s3 = g_eidx[j + 3];
        float4 a = zz[(size_t)s0 * 32 + lane];
        float4 b = zz[(size_t)s1 * 32 + lane];
        float4 c = zz[(size_t)s2 * 32 + lane];
        float4 d = zz[(size_t)s3 * 32 + lane];
        add4(acc, a); add4(acc, b); add4(acc, c); add4(acc, d);
    }
    for (; j < end; j++)
        add4(acc, zz[(size_t)g_eidx[j] * 32 + lane]);
    ((float4*)g_agg)[(size_t)node * 32 + lane] = acc;
}

// ---------------- gather layer 2 + log_softmax, fused (warp per node) ---------
__global__ void k_gather_out(float* __restrict__ out) {
    int node = (blockIdx.x * blockDim.x + threadIdx.x) >> 5;
    int lane = threadIdx.x & 31;
    if (node >= N_NODES) return;
    const bool act = (lane < DOUT / 4);
    int beg = g_rowptr[node];
    int end = g_rowptr[node + 1];
    const float* u = sel(1);
    float4 acc = make_float4(0.f, 0.f, 0.f, 0.f);
    int j = beg;
    for (; j + 3 < end; j += 4) {
        int s0 = g_eidx[j], s1 = g_eidx[j + 1];
        int s2 = g_eidx[j + 2], s3 = g_eidx[j + 3];
        if (act) {
            float4 a = ((const float4*)(u + (size_t)s0 * DOUT))[lane];
            float4 b = ((const float4*)(u + (size_t)s1 * DOUT))[lane];
            float4 c = ((const float4*)(u + (size_t)s2 * DOUT))[lane];
            float4 d = ((const float4*)(u + (size_t)s3 * DOUT))[lane];
            add4(acc, a); add4(acc, b); add4(acc, c); add4(acc, d);
        }
    }
    for (; j < end; j++)
        if (act)
            add4(acc, ((const float4*)(u + (size_t)g_eidx[j] * DOUT))[lane]);

    float inv = g_inv[node];
    float4 x = make_float4(0.f, 0.f, 0.f, 0.f);
    if (act) {
        float4 v = ((const float4*)(sel(2) + (size_t)node * DOUT))[lane];
        x.x = fmaf(acc.x, inv, v.x);
        x.y = fmaf(acc.y, inv, v.y);
        x.z = fmaf(acc.z, inv, v.z);
        x.w = fmaf(acc.w, inv, v.w);
    }
    float m = act ? fmaxf(fmaxf(x.x, x.y), fmaxf(x.z, x.w)) : -INFINITY;
#pragma unroll
    for (int o = 16; o; o >>= 1) m = fmaxf(m, __shfl_xor_sync(~0u, m, o));
    float s = act ? (expf(x.x - m) + expf(x.y - m) + expf(x.z - m) + expf(x.w - m))
                  : 0.f;
#pragma unroll
    for (int o = 16; o; o >>= 1) s += __shfl_xor_sync(~0u, s, o);
    float lse = m + logf(s);
    if (act) {
        float4 r = make_float4(x.x - lse, x.y - lse, x.z - lse, x.w - lse);
        ((float4*)(out + (size_t)node * DOUT))[lane] = r;
    }
}

// ---------------- launch: kernel launches ONLY (graph-capture safe) -----------
extern "C" void kernel_launch(void* const* d_in, const int* in_sizes, int n_in,
                              void* d_out, int out_size) {
    const float* x   = (const float*)d_in[0];
    const int*   ei  = (const int*)d_in[1];   // int32 (JAX default: no x64)
    const float* W1l = (const float*)d_in[2];
    const float* W1r = (const float*)d_in[3];
    const float* b1  = (const float*)d_in[4];
    const float* W2l = (const float*)d_in[5];
    const float* W2r = (const float*)d_in[6];
    const float* b2  = (const float*)d_in[7];
    float* out = (float*)d_out;

    const int gb = (N_NODES + 127) / 128;       // 782 row-blocks
    const int ge = (N_EDGES + 255) / 256;
    const int gw = (N_NODES * 32 + 255) / 256;  // warp-per-node grid
    const dim3 gt(gb, 2);                       // tensor GEMM grid (2 N-halves)

    // bf16 hi/lo images (x and both layer-1 weights)
    k_prepx<<<(int)(((size_t)N_NODES * D / 2 + 255) / 256), 256>>>(x);
    k_prepw<<<2, 256>>>(W1l, W1r);

    // CSR build (multi-block deterministic scan)
    k_zero_deg<<<(N_NODES + 255) / 256, 256>>>();
    k_deg<<<ge, 256>>>(ei);
    k_s1<<<SCAN_BLKS, 256>>>();
    k_s2<<<1, 128>>>();
    k_s3<<<SCAN_BLKS, 256>>>();
    k_fill<<<ge, 256>>>(ei);

    // layer 1: z = x@W1l (HMMA) ; agg = gather(z) ; h = relu(x@W1r+b1+agg*inv)
    tmma<0><<<gt, 256>>>(0, nullptr, N_NODES);
    k_gather128<<<gw, 256>>>();
    tmma<1><<<gt, 256>>>(1, b1, N_NODES);

    // layer 2: [u|v] = h @ [W2l|W2r] (+b2 on v), then fused gather+log_softmax
    sgemm2<<<gb, 256>>>(W2l, W2r, b2, N_NODES);
    k_gather_out<<<gw, 256>>>(out);
}

// round 16
// speedup vs baseline: 1.5697x; 1.0120x over previous
#include <cuda_runtime.h>
#include <cuda_bf16.h>
#include <cuda_fp16.h>
#include <math.h>
#include <cstdint>

#define N_NODES 100000
#define N_EDGES 3200000
#define D       128
#define DOUT    40

#define SCAN_BLKS ((N_NODES + 1023) / 1024)   // 98

// ---------------- scratch (device globals; referenced ONLY from device code) --
__device__ float  g_z  [(size_t)N_NODES * D];  // h = relu(...) (fp32, layer-2 A)
__device__ __half g_zh [(size_t)N_NODES * D];  // z = x@W1_l in fp16 (gather input)
__device__ float  g_agg[(size_t)N_NODES * D];  // agg (layer1); later u | v
__device__ float  g_inv[N_NODES];
__device__ int    g_deg[N_NODES];
__device__ int    g_rowptr[N_NODES + 1];
__device__ int    g_cur[N_NODES];
__device__ int    g_eidx[N_EDGES];
__device__ int    g_bsum[128];
__device__ int    g_boff[128];
// bf16 hi/lo split images
__device__ __nv_bfloat16 g_xhi[(size_t)N_NODES * D];
__device__ __nv_bfloat16 g_xlo[(size_t)N_NODES * D];
// W images: [mat(2)][part hi/lo(2)][n(128)][k(128)] bf16, k-contiguous
__device__ __nv_bfloat16 g_wt[2 * 2 * 128 * 128];

// 0: g_z (h)  1: u region  2: v region
__device__ __forceinline__ float* sel(int id) {
    if (id == 0) return g_z;
    if (id == 1) return g_agg;
    return g_agg + (size_t)N_NODES * DOUT;
}

// ---------------- CSR build ---------------------------------------------------
__global__ void k_zero_deg() {
    int i = blockIdx.x * blockDim.x + threadIdx.x;
    if (i < N_NODES) g_deg[i] = 0;
}

__global__ void k_deg(const int* __restrict__ ei) {
    int e = blockIdx.x * blockDim.x + threadIdx.x;
    if (e < N_EDGES) atomicAdd(&g_deg[ei[N_EDGES + e]], 1);
}

__device__ __forceinline__ int warp_iscan(int v, int lane) {
#pragma unroll
    for (int off = 1; off < 32; off <<= 1) {
        int t = __shfl_up_sync(~0u, v, off);
        if (lane >= off) v += t;
    }
    return v;
}

__global__ __launch_bounds__(256) void k_s1() {
    __shared__ int wsum[8];
    int t = threadIdx.x, lane = t & 31, wid = t >> 5;
    int i0 = blockIdx.x * 1024 + t * 4;
    int s = 0;
#pragma unroll
    for (int k = 0; k < 4; k++) {
        int i = i0 + k;
        if (i < N_NODES) s += g_deg[i];
    }
#pragma unroll
    for (int o = 16; o; o >>= 1) s += __shfl_xor_sync(~0u, s, o);
    if (lane == 0) wsum[wid] = s;
    __syncthreads();
    if (wid == 0) {
        int v = (lane < 8) ? wsum[lane] : 0;
#pragma unroll
        for (int o = 4; o; o >>= 1) v += __shfl_xor_sync(~0u, v, o);
        if (t == 0) g_bsum[blockIdx.x] = v;
    }
}

__global__ __launch_bounds__(128) void k_s2() {
    __shared__ int wsum[4];
    int t = threadIdx.x, lane = t & 31, wid = t >> 5;
    int v = (t < SCAN_BLKS) ? g_bsum[t] : 0;
    int incl = warp_iscan(v, lane);
    if (lane == 31) wsum[wid] = incl;
    __syncthreads();
    if (wid == 0) {
        int s = (lane < 4) ? wsum[lane] : 0;
        s = warp_iscan(s, lane);
        if (lane < 4) wsum[lane] = s;
    }
    __syncthreads();
    int excl = incl - v + (wid ? wsum[wid - 1] : 0);
    if (t < SCAN_BLKS) g_boff[t] = excl;
    if (t == 0) g_rowptr[N_NODES] = N_EDGES;
}

__global__ __launch_bounds__(256) void k_s3() {
    __shared__ int wsum[8];
    int t = threadIdx.x, lane = t & 31, wid = t >> 5;
    int i0 = blockIdx.x * 1024 + t * 4;
    int d[4];
    int ts = 0;
#pragma unroll
    for (int k = 0; k < 4; k++) {
        int i = i0 + k;
        d[k] = (i < N_NODES) ? g_deg[i] : 0;
        ts += d[k];
    }
    int incl = warp_iscan(ts, lane);
    if (lane == 31) wsum[wid] = incl;
    __syncthreads();
    if (wid == 0) {
        int s = (lane < 8) ? wsum[lane] : 0;
        s = warp_iscan(s, lane);
        if (lane < 8) wsum[lane] = s;
    }
    __syncthreads();
    int base = g_boff[blockIdx.x] + incl - ts + (wid ? wsum[wid - 1] : 0);
#pragma unroll
    for (int k = 0; k < 4; k++) {
        int i = i0 + k;
        if (i < N_NODES) {
            g_rowptr[i] = base;
            g_cur[i]    = base;
            g_inv[i]    = 1.0f / fmaxf((float)d[k], 1.0f);
        }
        base += d[k];
    }
}

__global__ void k_fill(const int* __restrict__ ei) {
    int e = blockIdx.x * blockDim.x + threadIdx.x;
    if (e >= N_EDGES) return;
    int s = ei[e];
    int dd = ei[N_EDGES + e];
    int pos = atomicAdd(&g_cur[dd], 1);
    g_eidx[pos] = s;
}

// ---------------- bf16 hi/lo prep ---------------------------------------------
__global__ void k_prepx(const float* __restrict__ x) {
    size_t i = (size_t)blockIdx.x * blockDim.x + threadIdx.x;   // pair index
    if (i >= (size_t)N_NODES * D / 2) return;
    float2 f = ((const float2*)x)[i];
    __nv_bfloat162 h2 = __floats2bfloat162_rn(f.x, f.y);
    float2 hf = __bfloat1622float2(h2);
    __nv_bfloat162 l2 = __floats2bfloat162_rn(f.x - hf.x, f.y - hf.y);
    ((__nv_bfloat162*)g_xhi)[i] = h2;
    ((__nv_bfloat162*)g_xlo)[i] = l2;
}

__global__ __launch_bounds__(256) void k_prepw(const float* __restrict__ W0,
                                               const float* __restrict__ W1)
{
    int mat = blockIdx.x;
    const float* W = mat ? W1 : W0;
    for (int idx = threadIdx.x; idx < 128 * 128; idx += 256) {
        int k = idx >> 7;
        int n = idx & 127;
        float v = W[(size_t)k * 128 + n];
        __nv_bfloat16 hb = __float2bfloat16(v);
        float hf = __bfloat162float(hb);
        __nv_bfloat16 lb = __float2bfloat16(v - hf);
        g_wt[((size_t)(mat * 2 + 0) * 128 + n) * 128 + k] = hb;
        g_wt[((size_t)(mat * 2 + 1) * 128 + n) * 128 + k] = lb;
    }
}

// ---------------- tensor-core GEMM via mma.sync (HMMA bf16, fp32 acc) ---------
// EPI 0: g_zh[M,128] (fp16) = x @ W_mat          (no bias)
// EPI 1: g_z [M,128] (fp32) = relu(x@W_mat + bias + g_agg*inv)
__device__ __forceinline__ void mma16816(float* c, const uint32_t* a,
                                         const uint32_t* b) {
    asm volatile(
        "mma.sync.aligned.m16n8k16.row.col.f32.bf16.bf16.f32 "
        "{%0,%1,%2,%3}, {%4,%5,%6,%7}, {%8,%9}, {%0,%1,%2,%3};"
        : "+f"(c[0]), "+f"(c[1]), "+f"(c[2]), "+f"(c[3])
        : "r"(a[0]), "r"(a[1]), "r"(a[2]), "r"(a[3]), "r"(b[0]), "r"(b[1]));
}

template <int EPI>
__global__ __launch_bounds__(256) void tmma(int mat, const float* __restrict__ bias,
                                            int M)
{
    constexpr int PAD = 40;                     // 80B row pitch: conflict-free frags
    __shared__ __align__(16) __nv_bfloat16 sA[2][128][PAD];
    __shared__ __align__(16) __nv_bfloat16 sB[2][64][PAD];

    const int tid  = threadIdx.x;
    const int wid  = tid >> 5;
    const int lane = tid & 31;
    const int wm   = wid >> 1;
    const int wn   = wid & 1;
    const int g    = lane >> 2;
    const int t4   = lane & 3;
    const int rowBase = blockIdx.x * 128;
    const int nh      = blockIdx.y;

    const __nv_bfloat16* Asrc[2] = { g_xhi, g_xlo };

    float acc[2][4][4];
#pragma unroll
    for (int mt = 0; mt < 2; mt++)
#pragma unroll
        for (int nt = 0; nt < 4; nt++)
#pragma unroll
            for (int q = 0; q < 4; q++) acc[mt][nt][q] = 0.f;

#pragma unroll
    for (int kc = 0; kc < 4; kc++) {           // K chunks of 32
        const int kb = kc * 32;
        if (kc) __syncthreads();
        for (int i = tid; i < 1024; i += 256) {
            int part = i >> 9, j = i & 511;
            int r = j >> 2, c = j & 3;
            int row = rowBase + r;
            uint4 v = make_uint4(0, 0, 0, 0);
            if (row < M)
                v = *(const uint4*)(Asrc[part] + (size_t)row * D + kb + c * 8);
            *(uint4*)&sA[part][r][c * 8] = v;
        }
        for (int i = tid; i < 512; i += 256) {
            int part = i >> 8, j = i & 255;
            int r = j >> 2, c = j & 3;
            *(uint4*)&sB[part][r][c * 8] =
                *(const uint4*)(g_wt + ((size_t)(mat * 2 + part) * 128 + nh * 64 + r) * 128
                                + kb + c * 8);
        }
        __syncthreads();

#pragma unroll
        for (int ks = 0; ks < 2; ks++) {
            const int k2 = ks * 16 + t4 * 2;
            uint32_t ah[2][4], al[2][4], bh[4][2], bl[4][2];
#pragma unroll
            for (int mt = 0; mt < 2; mt++) {
                int r = wm * 32 + mt * 16 + g;
                ah[mt][0] = *(const uint32_t*)&sA[0][r    ][k2];
                ah[mt][1] = *(const uint32_t*)&sA[0][r + 8][k2];
                ah[mt][2] = *(const uint32_t*)&sA[0][r    ][k2 + 8];
                ah[mt][3] = *(const uint32_t*)&sA[0][r + 8][k2 + 8];
                al[mt][0] = *(const uint32_t*)&sA[1][r    ][k2];
                al[mt][1] = *(const uint32_t*)&sA[1][r + 8][k2];
                al[mt][2] = *(const uint32_t*)&sA[1][r    ][k2 + 8];
                al[mt][3] = *(const uint32_t*)&sA[1][r + 8][k2 + 8];
            }
#pragma unroll
            for (int nt = 0; nt < 4; nt++) {
                int rn = wn * 32 + nt * 8 + g;
                bh[nt][0] = *(const uint32_t*)&sB[0][rn][k2];
                bh[nt][1] = *(const uint32_t*)&sB[0][rn][k2 + 8];
                bl[nt][0] = *(const uint32_t*)&sB[1][rn][k2];
                bl[nt][1] = *(const uint32_t*)&sB[1][rn][k2 + 8];
            }
#pragma unroll
            for (int mt = 0; mt < 2; mt++)
#pragma unroll
                for (int nt = 0; nt < 4; nt++) {
                    mma16816(acc[mt][nt], ah[mt], bh[nt]);   // hi*hi
                    mma16816(acc[mt][nt], al[mt], bh[nt]);   // lo*hi
                    mma16816(acc[mt][nt], ah[mt], bl[nt]);   // hi*lo
                }
        }
    }

#pragma unroll
    for (int mt = 0; mt < 2; mt++) {
        int r0 = rowBase + wm * 32 + mt * 16 + g;
#pragma unroll
        for (int half = 0; half < 2; half++) {
            int row = r0 + half * 8;
            if (row >= M) continue;
            float inv = (EPI == 1) ? g_inv[row] : 0.f;
#pragma unroll
            for (int nt = 0; nt < 4; nt++) {
                int col = nh * 64 + wn * 32 + nt * 8 + t4 * 2;
                float v0 = acc[mt][nt][half * 2 + 0];
                float v1 = acc[mt][nt][half * 2 + 1];
                if (EPI == 1) {
                    v0 += bias[col]; v1 += bias[col + 1];
                    const float* ag = g_agg + (size_t)row * D + col;
                    v0 = fmaxf(fmaf(ag[0], inv, v0), 0.f);
                    v1 = fmaxf(fmaf(ag[1], inv, v1), 0.f);
                    *(float2*)(g_z + (size_t)row * D + col) = make_float2(v0, v1);
                } else {
                    *(__half2*)(g_zh + (size_t)row * D + col) =
                        __floats2half2_rn(v0, v1);
                }
            }
        }
    }
}

// ---------------- merged layer-2 GEMM: [u | v] = h @ [W2l | W2r] (+b2 on v) ---
__global__ __launch_bounds__(256) void sgemm2(
    const float* __restrict__ W2l, const float* __restrict__ W2r,
    const float* __restrict__ b2, int M)
{
    constexpr int BM = 128, BN = 80, BK = 16, TM = 8, TN = 5, THREADS = 256;
    __shared__ float As[2][BK][BM + 4];
    __shared__ float Bs[2][BK][BN];

    const float* A = sel(0);   // h
    float* U = sel(1);
    float* V = sel(2);

    const int tid     = threadIdx.x;
    const int rowBase = blockIdx.x * BM;
    const int tcol    = tid % (BN / TN);   // 16
    const int trow    = tid / (BN / TN);   // 16

    float4 pa[2];
    float  pb[5];

    auto load_stage = [&](int kt) {
#pragma unroll
        for (int s = 0; s < 2; s++) {
            int i  = tid + s * THREADS;
            int am = i / (BK / 4);
            int ak = (i % (BK / 4)) * 4;
            int row = rowBase + am;
            pa[s] = (row < M)
                ? *(const float4*)(A + (size_t)row * D + kt * BK + ak)
                : make_float4(0.f, 0.f, 0.f, 0.f);
        }
#pragma unroll
        for (int s = 0; s < 5; s++) {
            int j  = tid + s * THREADS;
            int bk = j / BN;
            int bj = j % BN;
            int krow = kt * BK + bk;
            pb[s] = (bj < DOUT) ? W2l[(size_t)krow * DOUT + bj]
                                : W2r[(size_t)krow * DOUT + (bj - DOUT)];
        }
    };
    auto store_stage = [&](int buf) {
#pragma unroll
        for (int s = 0; s < 2; s++) {
            int i  = tid + s * THREADS;
            int am = i / (BK / 4);
            int ak = (i % (BK / 4)) * 4;
            As[buf][ak + 0][am] = pa[s].x; As[buf][ak + 1][am] = pa[s].y;
            As[buf][ak + 2][am] = pa[s].z; As[buf][ak + 3][am] = pa[s].w;
        }
#pragma unroll
        for (int s = 0; s < 5; s++) {
            int j = tid + s * THREADS;
            Bs[buf][j / BN][j % BN] = pb[s];
        }
    };

    float acc[TM][TN];
#pragma unroll
    for (int i = 0; i < TM; i++)
#pragma unroll
        for (int j = 0; j < TN; j++) acc[i][j] = 0.f;

    load_stage(0);
    store_stage(0);

    constexpr int NKT = D / BK;
#pragma unroll
    for (int kt = 0; kt < NKT; kt++) {
        __syncthreads();
        int buf = kt & 1;
        if (kt < NKT - 1) load_stage(kt + 1);
#pragma unroll
        for (int k = 0; k < BK; k++) {
            float ra[TM], rb[TN];
#pragma unroll
            for (int i = 0; i < TM; i++) ra[i] = As[buf][k][trow * TM + i];
#pragma unroll
            for (int j = 0; j < TN; j++) rb[j] = Bs[buf][k][tcol * TN + j];
#pragma unroll
            for (int i = 0; i < TM; i++)
#pragma unroll
                for (int j = 0; j < TN; j++) acc[i][j] += ra[i] * rb[j];
        }
        if (kt < NKT - 1) store_stage(buf ^ 1);
    }

#pragma unroll
    for (int i = 0; i < TM; i++) {
        int row = rowBase + trow * TM + i;
        if (row >= M) continue;
#pragma unroll
        for (int j = 0; j < TN; j++) {
            int c = tcol * TN + j;
            if (c < DOUT)
                U[(size_t)row * DOUT + c] = acc[i][j];
            else
                V[(size_t)row * DOUT + (c - DOUT)] = acc[i][j] + b2[c - DOUT];
        }
    }
}

// ---------------- gather layer 1: warp per node, fp16 rows (256B/edge) --------
__global__ void k_gather128() {
    int node = (blockIdx.x * blockDim.x + threadIdx.x) >> 5;
    int lane = threadIdx.x & 31;
    if (node >= N_NODES) return;
    int beg = g_rowptr[node];
    int end = g_rowptr[node + 1];
    const __half2* zz = (const __half2*)g_zh;   // row = 64 half2
    float4 acc = make_float4(0.f, 0.f, 0.f, 0.f);

    auto accum = [&](int s) {
        // lane owns halves [lane*4, lane*4+4) = half2 pair at 2*lane
        uint2 raw = *(const uint2*)(zz + (size_t)s * 64 + lane * 2);
        __half2 p0 = *(__half2*)&raw.x;
        __half2 p1 = *(__half2*)&raw.y;
        float2 f0 = __half22float2(p0);
        float2 f1 = __half22float2(p1);
        acc.x += f0.x; acc.y += f0.y; acc.z += f1.x; acc.w += f1.y;
    };

    int j = beg;
    for (; j + 3 < end; j += 4) {
        int s0 = g_eidx[j], s1 = g_eidx[j + 1];
        int s2 = g_eidx[j + 2], s3 = g_eidx[j + 3];
        accum(s0); accum(s1); accum(s2); accum(s3);
    }
    for (; j < end; j++) accum(g_eidx[j]);
    ((float4*)g_agg)[(size_t)node * 32 + lane] = acc;
}

// ---------------- gather layer 2 + log_softmax, fused (warp per node) ---------
__device__ __forceinline__ void add4(float4& a, const float4 b) {
    a.x += b.x; a.y += b.y; a.z += b.z; a.w += b.w;
}

__global__ void k_gather_out(float* __restrict__ out) {
    int node = (blockIdx.x * blockDim.x + threadIdx.x) >> 5;
    int lane = threadIdx.x & 31;
    if (node >= N_NODES) return;
    const bool act = (lane < DOUT / 4);
    int beg = g_rowptr[node];
    int end = g_rowptr[node + 1];
    const float* u = sel(1);
    float4 acc = make_float4(0.f, 0.f, 0.f, 0.f);
    int j = beg;
    for (; j + 3 < end; j += 4) {
        int s0 = g_eidx[j], s1 = g_eidx[j + 1];
        int s2 = g_eidx[j + 2], s3 = g_eidx[j + 3];
        if (act) {
            float4 a = ((const float4*)(u + (size_t)s0 * DOUT))[lane];
            float4 b = ((const float4*)(u + (size_t)s1 * DOUT))[lane];
            float4 c = ((const float4*)(u + (size_t)s2 * DOUT))[lane];
            float4 d = ((const float4*)(u + (size_t)s3 * DOUT))[lane];
            add4(acc, a); add4(acc, b); add4(acc, c); add4(acc, d);
        }
    }
    for (; j < end; j++)
        if (act)
            add4(acc, ((const float4*)(u + (size_t)g_eidx[j] * DOUT))[lane]);

    float inv = g_inv[node];
    float4 x = make_float4(0.f, 0.f, 0.f, 0.f);
    if (act) {
        float4 v = ((const float4*)(sel(2) + (size_t)node * DOUT))[lane];
        x.x = fmaf(acc.x, inv, v.x);
        x.y = fmaf(acc.y, inv, v.y);
        x.z = fmaf(acc.z, inv, v.z);
        x.w = fmaf(acc.w, inv, v.w);
    }
    float m = act ? fmaxf(fmaxf(x.x, x.y), fmaxf(x.z, x.w)) : -INFINITY;
#pragma unroll
    for (int o = 16; o; o >>= 1) m = fmaxf(m, __shfl_xor_sync(~0u, m, o));
    float s = act ? (expf(x.x - m) + expf(x.y - m) + expf(x.z - m) + expf(x.w - m))
                  : 0.f;
#pragma unroll
    for (int o = 16; o; o >>= 1) s += __shfl_xor_sync(~0u, s, o);
    float lse = m + logf(s);
    if (act) {
        float4 r = make_float4(x.x - lse, x.y - lse, x.z - lse, x.w - lse);
        ((float4*)(out + (size_t)node * DOUT))[lane] = r;
    }
}

// ---------------- launch: kernel launches ONLY (graph-capture safe) -----------
extern "C" void kernel_launch(void* const* d_in, const int* in_sizes, int n_in,
                              void* d_out, int out_size) {
    const float* x   = (const float*)d_in[0];
    const int*   ei  = (const int*)d_in[1];   // int32 (JAX default: no x64)
    const float* W1l = (const float*)d_in[2];
    const float* W1r = (const float*)d_in[3];
    const float* b1  = (const float*)d_in[4];
    const float* W2l = (const float*)d_in[5];
    const float* W2r = (const float*)d_in[6];
    const float* b2  = (const float*)d_in[7];
    float* out = (float*)d_out;

    const int gb = (N_NODES + 127) / 128;       // 782 row-blocks
    const int ge = (N_EDGES + 255) / 256;
    const int gw = (N_NODES * 32 + 255) / 256;  // warp-per-node grid
    const dim3 gt(gb, 2);                       // tensor GEMM grid (2 N-halves)

    // bf16 hi/lo images (x and both layer-1 weights)
    k_prepx<<<(int)(((size_t)N_NODES * D / 2 + 255) / 256), 256>>>(x);
    k_prepw<<<2, 256>>>(W1l, W1r);

    // CSR build (multi-block deterministic scan)
    k_zero_deg<<<(N_NODES + 255) / 256, 256>>>();
    k_deg<<<ge, 256>>>(ei);
    k_s1<<<SCAN_BLKS, 256>>>();
    k_s2<<<1, 128>>>();
    k_s3<<<SCAN_BLKS, 256>>>();
    k_fill<<<ge, 256>>>(ei);

    // layer 1: z(fp16) = x@W1l ; agg = gather(z) ; h = relu(x@W1r+b1+agg*inv)
    tmma<0><<<gt, 256>>>(0, nullptr, N_NODES);
    k_gather128<<<gw, 256>>>();
    tmma<1><<<gt, 256>>>(1, b1, N_NODES);

    // layer 2: [u|v] = h @ [W2l|W2r] (+b2 on v), then fused gather+log_softmax
    sgemm2<<<gb, 256>>>(W2l, W2r, b2, N_NODES);
    k_gather_out<<<gw, 256>>>(out);
}

// round 17
// speedup vs baseline: 1.7187x; 1.0949x over previous
#include <cuda_runtime.h>
#include <cuda_bf16.h>
#include <cuda_fp16.h>
#include <math.h>
#include <cstdint>

#define N_NODES 100000
#define N_EDGES 3200000
#define D       128
#define DOUT    40

#define SCAN_BLKS ((N_NODES + 1023) / 1024)   // 98

// ---------------- scratch (device globals; referenced ONLY from device code) --
__device__ __half g_zh [(size_t)N_NODES * D];  // z = x@W1_l in fp16 (gather input)
__device__ float  g_agg[(size_t)N_NODES * D];  // agg (layer1); later v region
__device__ __half g_uh [(size_t)N_NODES * DOUT]; // u = h@W2_l in fp16
__device__ float  g_inv[N_NODES];
__device__ int    g_deg[N_NODES];
__device__ int    g_rowptr[N_NODES + 1];
__device__ int    g_cur[N_NODES];
__device__ int    g_eidx[N_EDGES];
__device__ int    g_bsum[128];
__device__ int    g_boff[128];
// bf16 hi/lo split images
__device__ __nv_bfloat16 g_xhi[(size_t)N_NODES * D];
__device__ __nv_bfloat16 g_xlo[(size_t)N_NODES * D];
__device__ __nv_bfloat16 g_hhi[(size_t)N_NODES * D];
__device__ __nv_bfloat16 g_hlo[(size_t)N_NODES * D];
// W1 images: [mat(2)][part(2)][n(128)][k(128)]; W2 image: [part(2)][n(80)][k(128)]
__device__ __nv_bfloat16 g_wt[2 * 2 * 128 * 128];
__device__ __nv_bfloat16 g_w2[2 * 80 * 128];

__device__ __forceinline__ float* vreg() {          // v = h@W2_r + b2 (fp32)
    return g_agg + (size_t)N_NODES * DOUT;
}

// ---------------- CSR build ---------------------------------------------------
__global__ void k_deg(const int* __restrict__ ei) {
    int e = blockIdx.x * blockDim.x + threadIdx.x;
    if (e < N_EDGES) atomicAdd(&g_deg[ei[N_EDGES + e]], 1);
}

__device__ __forceinline__ int warp_iscan(int v, int lane) {
#pragma unroll
    for (int off = 1; off < 32; off <<= 1) {
        int t = __shfl_up_sync(~0u, v, off);
        if (lane >= off) v += t;
    }
    return v;
}

__global__ __launch_bounds__(256) void k_s1() {
    __shared__ int wsum[8];
    int t = threadIdx.x, lane = t & 31, wid = t >> 5;
    int i0 = blockIdx.x * 1024 + t * 4;
    int s = 0;
#pragma unroll
    for (int k = 0; k < 4; k++) {
        int i = i0 + k;
        if (i < N_NODES) s += g_deg[i];
    }
#pragma unroll
    for (int o = 16; o; o >>= 1) s += __shfl_xor_sync(~0u, s, o);
    if (lane == 0) wsum[wid] = s;
    __syncthreads();
    if (wid == 0) {
        int v = (lane < 8) ? wsum[lane] : 0;
#pragma unroll
        for (int o = 4; o; o >>= 1) v += __shfl_xor_sync(~0u, v, o);
        if (t == 0) g_bsum[blockIdx.x] = v;
    }
}

__global__ __launch_bounds__(128) void k_s2() {
    __shared__ int wsum[4];
    int t = threadIdx.x, lane = t & 31, wid = t >> 5;
    int v = (t < SCAN_BLKS) ? g_bsum[t] : 0;
    int incl = warp_iscan(v, lane);
    if (lane == 31) wsum[wid] = incl;
    __syncthreads();
    if (wid == 0) {
        int s = (lane < 4) ? wsum[lane] : 0;
        s = warp_iscan(s, lane);
        if (lane < 4) wsum[lane] = s;
    }
    __syncthreads();
    int excl = incl - v + (wid ? wsum[wid - 1] : 0);
    if (t < SCAN_BLKS) g_boff[t] = excl;
    if (t == 0) g_rowptr[N_NODES] = N_EDGES;
}

__global__ __launch_bounds__(256) void k_s3() {
    __shared__ int wsum[8];
    int t = threadIdx.x, lane = t & 31, wid = t >> 5;
    int i0 = blockIdx.x * 1024 + t * 4;
    int d[4];
    int ts = 0;
#pragma unroll
    for (int k = 0; k < 4; k++) {
        int i = i0 + k;
        d[k] = (i < N_NODES) ? g_deg[i] : 0;
        ts += d[k];
    }
    int incl = warp_iscan(ts, lane);
    if (lane == 31) wsum[wid] = incl;
    __syncthreads();
    if (wid == 0) {
        int s = (lane < 8) ? wsum[lane] : 0;
        s = warp_iscan(s, lane);
        if (lane < 8) wsum[lane] = s;
    }
    __syncthreads();
    int base = g_boff[blockIdx.x] + incl - ts + (wid ? wsum[wid - 1] : 0);
#pragma unroll
    for (int k = 0; k < 4; k++) {
        int i = i0 + k;
        if (i < N_NODES) {
            g_rowptr[i] = base;
            g_cur[i]    = base;
            g_inv[i]    = 1.0f / fmaxf((float)d[k], 1.0f);
        }
        base += d[k];
    }
}

__global__ void k_fill(const int* __restrict__ ei) {
    int e = blockIdx.x * blockDim.x + threadIdx.x;
    if (e >= N_EDGES) return;
    int s = ei[e];
    int dd = ei[N_EDGES + e];
    int pos = atomicAdd(&g_cur[dd], 1);
    g_eidx[pos] = s;
}

// ---------------- bf16 hi/lo prep (also zeros g_deg) ---------------------------
__global__ void k_prepx(const float* __restrict__ x) {
    size_t i = (size_t)blockIdx.x * blockDim.x + threadIdx.x;   // pair index
    if (i < N_NODES) g_deg[i] = 0;          // grid >> N_NODES: covered
    if (i >= (size_t)N_NODES * D / 2) return;
    float2 f = ((const float2*)x)[i];
    __nv_bfloat162 h2 = __floats2bfloat162_rn(f.x, f.y);
    float2 hf = __bfloat1622float2(h2);
    __nv_bfloat162 l2 = __floats2bfloat162_rn(f.x - hf.x, f.y - hf.y);
    ((__nv_bfloat162*)g_xhi)[i] = h2;
    ((__nv_bfloat162*)g_xlo)[i] = l2;
}

// blocks 0,1: W1l/W1r -> g_wt ; block 2: [W2l|W2r] -> g_w2
__global__ __launch_bounds__(256) void k_prepw(const float* __restrict__ W0,
                                               const float* __restrict__ W1,
                                               const float* __restrict__ W2l,
                                               const float* __restrict__ W2r)
{
    int mat = blockIdx.x;
    if (mat < 2) {
        const float* W = mat ? W1 : W0;
        for (int idx = threadIdx.x; idx < 128 * 128; idx += 256) {
            int k = idx >> 7;
            int n = idx & 127;
            float v = W[(size_t)k * 128 + n];
            __nv_bfloat16 hb = __float2bfloat16(v);
            float hf = __bfloat162float(hb);
            __nv_bfloat16 lb = __float2bfloat16(v - hf);
            g_wt[((size_t)(mat * 2 + 0) * 128 + n) * 128 + k] = hb;
            g_wt[((size_t)(mat * 2 + 1) * 128 + n) * 128 + k] = lb;
        }
    } else {
        for (int idx = threadIdx.x; idx < 80 * 128; idx += 256) {
            int n = idx >> 7;          // 0..79
            int k = idx & 127;
            float v = (n < DOUT) ? W2l[(size_t)k * DOUT + n]
                                 : W2r[(size_t)k * DOUT + (n - DOUT)];
            __nv_bfloat16 hb = __float2bfloat16(v);
            float hf = __bfloat162float(hb);
            __nv_bfloat16 lb = __float2bfloat16(v - hf);
            g_w2[((size_t)0 * 80 + n) * 128 + k] = hb;
            g_w2[((size_t)1 * 80 + n) * 128 + k] = lb;
        }
    }
}

// ---------------- HMMA helpers -------------------------------------------------
__device__ __forceinline__ void mma16816(float* c, const uint32_t* a,
                                         const uint32_t* b) {
    asm volatile(
        "mma.sync.aligned.m16n8k16.row.col.f32.bf16.bf16.f32 "
        "{%0,%1,%2,%3}, {%4,%5,%6,%7}, {%8,%9}, {%0,%1,%2,%3};"
        : "+f"(c[0]), "+f"(c[1]), "+f"(c[2]), "+f"(c[3])
        : "r"(a[0]), "r"(a[1]), "r"(a[2]), "r"(a[3]), "r"(b[0]), "r"(b[1]));
}

// ---------------- layer-1 GEMM (HMMA bf16 hi/lo, fp32 acc) --------------------
// EPI 0: g_zh[M,128] (fp16) = x @ W_mat
// EPI 1: h = relu(x@W_mat + bias + g_agg*inv) -> g_hhi/g_hlo (bf16 split)
template <int EPI>
__global__ __launch_bounds__(256) void tmma(int mat, const float* __restrict__ bias,
                                            int M)
{
    constexpr int PAD = 40;
    __shared__ __align__(16) __nv_bfloat16 sA[2][128][PAD];
    __shared__ __align__(16) __nv_bfloat16 sB[2][64][PAD];

    const int tid  = threadIdx.x;
    const int wid  = tid >> 5;
    const int lane = tid & 31;
    const int wm   = wid >> 1;
    const int wn   = wid & 1;
    const int g    = lane >> 2;
    const int t4   = lane & 3;
    const int rowBase = blockIdx.x * 128;
    const int nh      = blockIdx.y;

    const __nv_bfloat16* Asrc[2] = { g_xhi, g_xlo };

    float acc[2][4][4];
#pragma unroll
    for (int mt = 0; mt < 2; mt++)
#pragma unroll
        for (int nt = 0; nt < 4; nt++)
#pragma unroll
            for (int q = 0; q < 4; q++) acc[mt][nt][q] = 0.f;

#pragma unroll
    for (int kc = 0; kc < 4; kc++) {
        const int kb = kc * 32;
        if (kc) __syncthreads();
        for (int i = tid; i < 1024; i += 256) {
            int part = i >> 9, j = i & 511;
            int r = j >> 2, c = j & 3;
            int row = rowBase + r;
            uint4 v = make_uint4(0, 0, 0, 0);
            if (row < M)
                v = *(const uint4*)(Asrc[part] + (size_t)row * D + kb + c * 8);
            *(uint4*)&sA[part][r][c * 8] = v;
        }
        for (int i = tid; i < 512; i += 256) {
            int part = i >> 8, j = i & 255;
            int r = j >> 2, c = j & 3;
            *(uint4*)&sB[part][r][c * 8] =
                *(const uint4*)(g_wt + ((size_t)(mat * 2 + part) * 128 + nh * 64 + r) * 128
                                + kb + c * 8);
        }
        __syncthreads();

#pragma unroll
        for (int ks = 0; ks < 2; ks++) {
            const int k2 = ks * 16 + t4 * 2;
            uint32_t ah[2][4], al[2][4], bh[4][2], bl[4][2];
#pragma unroll
            for (int mt = 0; mt < 2; mt++) {
                int r = wm * 32 + mt * 16 + g;
                ah[mt][0] = *(const uint32_t*)&sA[0][r    ][k2];
                ah[mt][1] = *(const uint32_t*)&sA[0][r + 8][k2];
                ah[mt][2] = *(const uint32_t*)&sA[0][r    ][k2 + 8];
                ah[mt][3] = *(const uint32_t*)&sA[0][r + 8][k2 + 8];
                al[mt][0] = *(const uint32_t*)&sA[1][r    ][k2];
                al[mt][1] = *(const uint32_t*)&sA[1][r + 8][k2];
                al[mt][2] = *(const uint32_t*)&sA[1][r    ][k2 + 8];
                al[mt][3] = *(const uint32_t*)&sA[1][r + 8][k2 + 8];
            }
#pragma unroll
            for (int nt = 0; nt < 4; nt++) {
                int rn = wn * 32 + nt * 8 + g;
                bh[nt][0] = *(const uint32_t*)&sB[0][rn][k2];
                bh[nt][1] = *(const uint32_t*)&sB[0][rn][k2 + 8];
                bl[nt][0] = *(const uint32_t*)&sB[1][rn][k2];
                bl[nt][1] = *(const uint32_t*)&sB[1][rn][k2 + 8];
            }
#pragma unroll
            for (int mt = 0; mt < 2; mt++)
#pragma unroll
                for (int nt = 0; nt < 4; nt++) {
                    mma16816(acc[mt][nt], ah[mt], bh[nt]);
                    mma16816(acc[mt][nt], al[mt], bh[nt]);
                    mma16816(acc[mt][nt], ah[mt], bl[nt]);
                }
        }
    }

#pragma unroll
    for (int mt = 0; mt < 2; mt++) {
        int r0 = rowBase + wm * 32 + mt * 16 + g;
#pragma unroll
        for (int half = 0; half < 2; half++) {
            int row = r0 + half * 8;
            if (row >= M) continue;
            float inv = (EPI == 1) ? g_inv[row] : 0.f;
#pragma unroll
            for (int nt = 0; nt < 4; nt++) {
                int col = nh * 64 + wn * 32 + nt * 8 + t4 * 2;
                float v0 = acc[mt][nt][half * 2 + 0];
                float v1 = acc[mt][nt][half * 2 + 1];
                if (EPI == 1) {
                    v0 += bias[col]; v1 += bias[col + 1];
                    const float* ag = g_agg + (size_t)row * D + col;
                    v0 = fmaxf(fmaf(ag[0], inv, v0), 0.f);
                    v1 = fmaxf(fmaf(ag[1], inv, v1), 0.f);
                    __nv_bfloat162 h2 = __floats2bfloat162_rn(v0, v1);
                    float2 hf = __bfloat1622float2(h2);
                    __nv_bfloat162 l2 = __floats2bfloat162_rn(v0 - hf.x, v1 - hf.y);
                    *(__nv_bfloat162*)(g_hhi + (size_t)row * D + col) = h2;
                    *(__nv_bfloat162*)(g_hlo + (size_t)row * D + col) = l2;
                } else {
                    *(__half2*)(g_zh + (size_t)row * D + col) =
                        __floats2half2_rn(v0, v1);
                }
            }
        }
    }
}

// ---------------- layer-2 GEMM (HMMA): [u(fp16) | v(fp32)] = h @ [W2l|W2r] ----
// BN = 80 (u 40 | v 40). 8 warps: wm=wid>>1 (32 rows), wn=wid&1 (40 cols, 5 tiles).
__global__ __launch_bounds__(256) void tmma2(const float* __restrict__ b2, int M)
{
    constexpr int PAD = 40;
    __shared__ __align__(16) __nv_bfloat16 sA[2][128][PAD];
    __shared__ __align__(16) __nv_bfloat16 sB[2][80][PAD];

    const int tid  = threadIdx.x;
    const int wid  = tid >> 5;
    const int lane = tid & 31;
    const int wm   = wid >> 1;
    const int wn   = wid & 1;
    const int g    = lane >> 2;
    const int t4   = lane & 3;
    const int rowBase = blockIdx.x * 128;

    const __nv_bfloat16* Asrc[2] = { g_hhi, g_hlo };

    float acc[2][5][4];
#pragma unroll
    for (int mt = 0; mt < 2; mt++)
#pragma unroll
        for (int nt = 0; nt < 5; nt++)
#pragma unroll
            for (int q = 0; q < 4; q++) acc[mt][nt][q] = 0.f;

#pragma unroll
    for (int kc = 0; kc < 4; kc++) {
        const int kb = kc * 32;
        if (kc) __syncthreads();
        for (int i = tid; i < 1024; i += 256) {
            int part = i >> 9, j = i & 511;
            int r = j >> 2, c = j & 3;
            int row = rowBase + r;
            uint4 v = make_uint4(0, 0, 0, 0);
            if (row < M)
                v = *(const uint4*)(Asrc[part] + (size_t)row * D + kb + c * 8);
            *(uint4*)&sA[part][r][c * 8] = v;
        }
        for (int i = tid; i < 640; i += 256) {
            int part = i / 320, j = i % 320;
            int r = j >> 2, c = j & 3;
            *(uint4*)&sB[part][r][c * 8] =
                *(const uint4*)(g_w2 + ((size_t)part * 80 + r) * 128 + kb + c * 8);
        }
        __syncthreads();

#pragma unroll
        for (int ks = 0; ks < 2; ks++) {
            const int k2 = ks * 16 + t4 * 2;
            uint32_t ah[2][4], al[2][4], bh[5][2], bl[5][2];
#pragma unroll
            for (int mt = 0; mt < 2; mt++) {
                int r = wm * 32 + mt * 16 + g;
                ah[mt][0] = *(const uint32_t*)&sA[0][r    ][k2];
                ah[mt][1] = *(const uint32_t*)&sA[0][r + 8][k2];
                ah[mt][2] = *(const uint32_t*)&sA[0][r    ][k2 + 8];
                ah[mt][3] = *(const uint32_t*)&sA[0][r + 8][k2 + 8];
                al[mt][0] = *(const uint32_t*)&sA[1][r    ][k2];
                al[mt][1] = *(const uint32_t*)&sA[1][r + 8][k2];
                al[mt][2] = *(const uint32_t*)&sA[1][r    ][k2 + 8];
                al[mt][3] = *(const uint32_t*)&sA[1][r + 8][k2 + 8];
            }
#pragma unroll
            for (int nt = 0; nt < 5; nt++) {
                int rn = wn * 40 + nt * 8 + g;
                bh[nt][0] = *(const uint32_t*)&sB[0][rn][k2];
                bh[nt][1] = *(const uint32_t*)&sB[0][rn][k2 + 8];
                bl[nt][0] = *(const uint32_t*)&sB[1][rn][k2];
                bl[nt][1] = *(const uint32_t*)&sB[1][rn][k2 + 8];
            }
#pragma unroll
            for (int mt = 0; mt < 2; mt++)
#pragma unroll
                for (int nt = 0; nt < 5; nt++) {
                    mma16816(acc[mt][nt], ah[mt], bh[nt]);
                    mma16816(acc[mt][nt], al[mt], bh[nt]);
                    mma16816(acc[mt][nt], ah[mt], bl[nt]);
                }
        }
    }

    float* V = vreg();
#pragma unroll
    for (int mt = 0; mt < 2; mt++) {
        int r0 = rowBase + wm * 32 + mt * 16 + g;
#pragma unroll
        for (int half = 0; half < 2; half++) {
            int row = r0 + half * 8;
            if (row >= M) continue;
#pragma unroll
            for (int nt = 0; nt < 5; nt++) {
                int col = wn * 40 + nt * 8 + t4 * 2;
                float v0 = acc[mt][nt][half * 2 + 0];
                float v1 = acc[mt][nt][half * 2 + 1];
                if (col < DOUT) {
                    *(__half2*)(g_uh + (size_t)row * DOUT + col) =
                        __floats2half2_rn(v0, v1);
                } else {
                    int c = col - DOUT;
                    *(float2*)(V + (size_t)row * DOUT + c) =
                        make_float2(v0 + b2[c], v1 + b2[c + 1]);
                }
            }
        }
    }
}

// ---------------- gather layer 1: warp per node, fp16 rows (256B/edge) --------
__global__ void k_gather128() {
    int node = (blockIdx.x * blockDim.x + threadIdx.x) >> 5;
    int lane = threadIdx.x & 31;
    if (node >= N_NODES) return;
    int beg = g_rowptr[node];
    int end = g_rowptr[node + 1];
    const __half2* zz = (const __half2*)g_zh;
    float4 acc = make_float4(0.f, 0.f, 0.f, 0.f);

    auto accum = [&](int s) {
        uint2 raw = *(const uint2*)(zz + (size_t)s * 64 + lane * 2);
        __half2 p0 = *(__half2*)&raw.x;
        __half2 p1 = *(__half2*)&raw.y;
        float2 f0 = __half22float2(p0);
        float2 f1 = __half22float2(p1);
        acc.x += f0.x; acc.y += f0.y; acc.z += f1.x; acc.w += f1.y;
    };

    int j = beg;
    for (; j + 3 < end; j += 4) {
        int s0 = g_eidx[j], s1 = g_eidx[j + 1];
        int s2 = g_eidx[j + 2], s3 = g_eidx[j + 3];
        accum(s0); accum(s1); accum(s2); accum(s3);
    }
    for (; j < end; j++) accum(g_eidx[j]);
    ((float4*)g_agg)[(size_t)node * 32 + lane] = acc;
}

// ---------------- gather layer 2 (fp16 u) + log_softmax, fused ----------------
__global__ void k_gather_out(float* __restrict__ out) {
    int node = (blockIdx.x * blockDim.x + threadIdx.x) >> 5;
    int lane = threadIdx.x & 31;
    if (node >= N_NODES) return;
    const bool act = (lane < DOUT / 4);   // lanes 0..9 own 4 cols each
    int beg = g_rowptr[node];
    int end = g_rowptr[node + 1];
    float4 acc = make_float4(0.f, 0.f, 0.f, 0.f);

    auto accum = [&](int s) {
        uint2 raw = *(const uint2*)(g_uh + (size_t)s * DOUT + lane * 4);
        __half2 p0 = *(__half2*)&raw.x;
        __half2 p1 = *(__half2*)&raw.y;
        float2 f0 = __half22float2(p0);
        float2 f1 = __half22float2(p1);
        acc.x += f0.x; acc.y += f0.y; acc.z += f1.x; acc.w += f1.y;
    };

    int j = beg;
    for (; j + 3 < end; j += 4) {
        int s0 = g_eidx[j], s1 = g_eidx[j + 1];
        int s2 = g_eidx[j + 2], s3 = g_eidx[j + 3];
        if (act) { accum(s0); accum(s1); accum(s2); accum(s3); }
    }
    for (; j < end; j++)
        if (act) accum(g_eidx[j]);

    float inv = g_inv[node];
    float4 x = make_float4(0.f, 0.f, 0.f, 0.f);
    if (act) {
        float4 v = ((const float4*)(vreg() + (size_t)node * DOUT))[lane];
        x.x = fmaf(acc.x, inv, v.x);
        x.y = fmaf(acc.y, inv, v.y);
        x.z = fmaf(acc.z, inv, v.z);
        x.w = fmaf(acc.w, inv, v.w);
    }
    float m = act ? fmaxf(fmaxf(x.x, x.y), fmaxf(x.z, x.w)) : -INFINITY;
#pragma unroll
    for (int o = 16; o; o >>= 1) m = fmaxf(m, __shfl_xor_sync(~0u, m, o));
    float s = act ? (expf(x.x - m) + expf(x.y - m) + expf(x.z - m) + expf(x.w - m))
                  : 0.f;
#pragma unroll
    for (int o = 16; o; o >>= 1) s += __shfl_xor_sync(~0u, s, o);
    float lse = m + logf(s);
    if (act) {
        float4 r = make_float4(x.x - lse, x.y - lse, x.z - lse, x.w - lse);
        ((float4*)(out + (size_t)node * DOUT))[lane] = r;
    }
}

// ---------------- launch: kernel launches ONLY (graph-capture safe) -----------
extern "C" void kernel_launch(void* const* d_in, const int* in_sizes, int n_in,
                              void* d_out, int out_size) {
    const float* x   = (const float*)d_in[0];
    const int*   ei  = (const int*)d_in[1];   // int32 (JAX default: no x64)
    const float* W1l = (const float*)d_in[2];
    const float* W1r = (const float*)d_in[3];
    const float* b1  = (const float*)d_in[4];
    const float* W2l = (const float*)d_in[5];
    const float* W2r = (const float*)d_in[6];
    const float* b2  = (const float*)d_in[7];
    float* out = (float*)d_out;

    const int gb = (N_NODES + 127) / 128;       // 782 row-blocks
    const int ge = (N_EDGES + 255) / 256;
    const int gw = (N_NODES * 32 + 255) / 256;  // warp-per-node grid
    const dim3 gt(gb, 2);                       // layer-1 GEMM grid (2 N-halves)

    // preps: x hi/lo split (+ deg zero), W1 + W2 images
    k_prepx<<<(int)(((size_t)N_NODES * D / 2 + 255) / 256), 256>>>(x);
    k_prepw<<<3, 256>>>(W1l, W1r, W2l, W2r);

    // CSR build (multi-block deterministic scan)
    k_deg<<<ge, 256>>>(ei);
    k_s1<<<SCAN_BLKS, 256>>>();
    k_s2<<<1, 128>>>();
    k_s3<<<SCAN_BLKS, 256>>>();
    k_fill<<<ge, 256>>>(ei);

    // layer 1: z(fp16) = x@W1l ; agg = gather(z) ; h(bf16 hi/lo) = relu(...)
    tmma<0><<<gt, 256>>>(0, nullptr, N_NODES);
    k_gather128<<<gw, 256>>>();
    tmma<1><<<gt, 256>>>(1, b1, N_NODES);

    // layer 2: [u(fp16)|v] = h @ [W2l|W2r] (+b2 on v), fused gather+log_softmax
    tmma2<<<gb, 256>>>(b2, N_NODES);
    k_gather_out<<<gw, 256>>>(out);
}